// round 3
// baseline (speedup 1.0000x reference)
#include <cuda_runtime.h>
#include <math.h>

#define NB 16
#define NT 2048
#define ND 512
#define NC 20
#define KE 40
#define KH 20
#define FEPS 1e-5f
#define LN2F 0.69314718055994531f

// ---------------- scratch ----------------
__device__ int            g_idx[NB][4][KE];   // 0=easy_act,1=easy_bkg,2=hard_act,3=hard_bkg
__device__ float          g_kl[NB][4];        // sums of 1/(dist+1); /800 at the end
__device__ double         g_distill_sum;
__device__ float          g_amax[NB];
__device__ unsigned char  g_abin[NB][NT];

// ---------------- helpers ----------------
__device__ __forceinline__ float warp_sum(float v) {
#pragma unroll
    for (int o = 16; o; o >>= 1) v += __shfl_down_sync(0xffffffffu, v, o);
    return v;
}
__device__ __forceinline__ float warp_max(float v) {
#pragma unroll
    for (int o = 16; o; o >>= 1) v = fmaxf(v, __shfl_down_sync(0xffffffffu, v, o));
    return v;
}
__device__ __forceinline__ unsigned long long pk2(float lo, float hi) {
    unsigned long long r;
    asm("mov.b64 %0, {%1, %2};" : "=l"(r) : "f"(lo), "f"(hi));
    return r;
}
__device__ __forceinline__ float2 upk2(unsigned long long v) {
    float2 f;
    asm("mov.b64 {%0, %1}, %2;" : "=f"(f.x), "=f"(f.y) : "l"(v));
    return f;
}
__device__ __forceinline__ unsigned long long ffma2(unsigned long long a,
                                                   unsigned long long b,
                                                   unsigned long long c) {
    unsigned long long d;
    asm("fma.rn.f32x2 %0, %1, %2, %3;" : "=l"(d) : "l"(a), "l"(b), "l"(c));
    return d;
}

// Descending radix select: bit pattern of the value at rank k (0-indexed, desc)
// among sc[0..n). All scores are >= 0 so bit order == value order.
// Requires n % blockDim.x == 0 (uniform warp trips for __match_any_sync).
__device__ unsigned radix_select_desc(const float* sc, int n, int k,
                                      unsigned* hist, unsigned* shc) {
    const int tid = threadIdx.x, nthr = blockDim.x;
    unsigned prefix = 0, pmask = 0;
#pragma unroll
    for (int level = 0; level < 4; ++level) {
        const int shift = 24 - 8 * level;
        for (int i = tid; i < 256; i += nthr) hist[i] = 0;
        __syncthreads();
        for (int i = tid; i < n; i += nthr) {
            unsigned u = __float_as_uint(sc[i]);
            bool ok = ((u & pmask) == prefix);
            unsigned d = ok ? ((u >> shift) & 255u) : 0x100u;
            unsigned mm = __match_any_sync(0xffffffffu, d);
            if (ok && ((tid & 31) == __ffs(mm) - 1))
                atomicAdd(&hist[d], (unsigned)__popc(mm));
        }
        __syncthreads();
        if (tid < 32) {
            const int l = tid;
            unsigned c[8]; unsigned lsum = 0;
#pragma unroll
            for (int i = 0; i < 8; ++i) { c[i] = hist[l * 8 + i]; lsum += c[i]; }
            unsigned v = lsum;
#pragma unroll
            for (int off = 1; off < 32; off <<= 1) {
                unsigned t = __shfl_down_sync(0xffffffffu, v, off);
                if (l + off < 32) v += t;
            }
            unsigned cum = v - lsum;          // elements in higher bins
            int found = -1; unsigned nk = 0;
#pragma unroll
            for (int i = 7; i >= 0; --i) {
                if (found < 0 && (unsigned)k >= cum && (unsigned)k < cum + c[i]) {
                    found = l * 8 + i; nk = (unsigned)k - cum;
                }
                cum += c[i];
            }
            if (found >= 0) { shc[0] = (unsigned)found; shc[1] = nk; }
        }
        __syncthreads();
        prefix |= shc[0] << shift;
        pmask  |= 0xFFu << shift;
        k = (int)shc[1];
        __syncthreads();
    }
    return prefix;
}

// ---------------- kernels ----------------
// Per batch: amax, exact median (ranks 1023/1024), abin; zero accumulators.
__global__ void __launch_bounds__(256) k_prep(const float* __restrict__ attn) {
    __shared__ float sa[NT];
    __shared__ unsigned hist[256];
    __shared__ unsigned shc[2];
    __shared__ float red[8];
    const int b = blockIdx.x, tid = threadIdx.x;
    float lmax = 0.f;
    for (int t = tid; t < NT; t += 256) {
        float v = attn[b * NT + t];
        sa[t] = v;
        lmax = fmaxf(lmax, v);
    }
    lmax = warp_max(lmax);
    if ((tid & 31) == 0) red[tid >> 5] = lmax;
    __syncthreads();
    if (tid == 0) {
        float m = red[0];
        for (int w = 1; w < 8; ++w) m = fmaxf(m, red[w]);
        g_amax[b] = m;
    }
    unsigned v1 = radix_select_desc(sa, NT, 1023, hist, shc);
    unsigned v2 = radix_select_desc(sa, NT, 1024, hist, shc);
    float med = 0.5f * (__uint_as_float(v1) + __uint_as_float(v2));
    for (int t = tid; t < NT; t += 256) g_abin[b][t] = (sa[t] > med) ? 1 : 0;
    if (tid < 4) g_kl[b][tid] = 0.f;
    if (b == 0 && tid == 0) g_distill_sum = 0.0;
}

// One block per (score_set, batch): radix-select top-K index set.
__global__ void __launch_bounds__(256) k_topk(const float* __restrict__ attn,
                                              const float* __restrict__ dmask) {
    __shared__ float ss[NT];
    __shared__ unsigned char sab[NT];
    __shared__ unsigned hist[256];
    __shared__ unsigned shc[2];
    __shared__ unsigned bm[NT / 32];
    __shared__ unsigned pfx[NT / 32];
    __shared__ int s_cnt;
    const int s = blockIdx.x, b = blockIdx.y, tid = threadIdx.x;
    const float amax = g_amax[b];
    if (s >= 2) {
        for (int t = tid; t < NT; t += 256) sab[t] = g_abin[b][t];
        __syncthreads();
    }
    for (int t = tid; t < NT; t += 256) {
        float a = attn[b * NT + t];
        float v;
        if (s == 0) v = a * dmask[b * NT + t];
        else if (s == 1) v = (amax - a) * dmask[b * NT + t];
        else {
            int bm3 = (t >= 3) ? (int)sab[t - 3] : 0;
            int bm2 = (t >= 2) ? (int)sab[t - 2] : 0;
            int bm1 = (t >= 1) ? (int)sab[t - 1] : 0;
            int b0  = (int)sab[t];
            int bp1 = (t + 1 < NT) ? (int)sab[t + 1] : 0;
            int bp2 = (t + 2 < NT) ? (int)sab[t + 2] : 0;
            int bp3 = (t + 3 < NT) ? (int)sab[t + 3] : 0;
            if (s == 2) {
                int er3 = bm1 & b0 & bp1;
                int er7 = er3 & bm3 & bm2 & bp2 & bp3;
                v = a * (float)(er3 & (er7 ^ 1));
            } else {
                int dl3 = bm1 | b0 | bp1;
                int dl7 = dl3 | bm3 | bm2 | bp2 | bp3;
                v = a * (float)(dl7 & (dl3 ^ 1));
            }
        }
        ss[t] = v;
    }
    if (tid == 0) s_cnt = 0;
    for (int i = tid; i < NT / 32; i += 256) bm[i] = 0;
    __syncthreads();
    const int K = (s < 2) ? KE : KH;
    unsigned vk = radix_select_desc(ss, NT, K - 1, hist, shc);
    const float fvk = __uint_as_float(vk);
    // collect: strictly-greater first (arbitrary order), ties by lowest index.
    for (int t = tid; t < NT; t += 256) {
        float v = ss[t];
        if (v > fvk) {
            int p = atomicAdd(&s_cnt, 1);
            g_idx[b][s][p] = t;
        } else if (v == fvk) {
            atomicOr(&bm[t >> 5], 1u << (t & 31));
        }
    }
    __syncthreads();
    if (tid < 32) {
        const int l = tid;
        unsigned p0 = __popc(bm[2 * l]), p1 = __popc(bm[2 * l + 1]);
        unsigned ls = p0 + p1, v = ls;
#pragma unroll
        for (int off = 1; off < 32; off <<= 1) {
            unsigned t2 = __shfl_up_sync(0xffffffffu, v, off);
            if (l >= off) v += t2;
        }
        unsigned excl = v - ls;
        pfx[2 * l] = excl;
        pfx[2 * l + 1] = excl + p0;
    }
    __syncthreads();
    const int base = s_cnt;
    const int m = K - base;
    for (int t = tid; t < NT; t += 256) {
        if (ss[t] == fvk) {
            int r = (int)(pfx[t >> 5] + __popc(bm[t >> 5] & ((1u << (t & 31)) - 1u)));
            if (r < m) g_idx[b][s][base + r] = t;
        }
    }
}

// grid (4, NB): blockIdx.x = qset*2 + qhalf. 320 threads = 10 warps.
// Each warp holds 4 p-rows (2 hard_act + 2 hard_bkg) in registers (u=mu^2+cov,
// w=-2mu packed f32x2); q half (20 rows r=1/cov, s=mu*r) staged in smem.
// dist = 0.5*(sum u*r + sum w*s) + Dq - 0.5*Lp - D/2, Dq = 0.5*(A_q + Lq).
__global__ void __launch_bounds__(320, 1) k_kl(const float* __restrict__ mu,
                                               const float* __restrict__ var) {
    extern __shared__ float sm[];
    float* r_q = sm;              // [20][ND]
    float* s_q = sm + 20 * ND;    // [20][ND]
    __shared__ float Dq[20];
    const int qs = blockIdx.x >> 1;
    const int qh = blockIdx.x & 1;
    const int b  = blockIdx.y;
    const int warp = threadIdx.x >> 5;   // 0..9
    const int lane = threadIdx.x & 31;

    // stage q (2 rows per warp)
    for (int j = warp; j < 20; j += 10) {
        const int idx = g_idx[b][qs][qh * 20 + j];
        const float4* mrow = (const float4*)(mu  + ((size_t)(b * NT + idx)) * ND);
        const float4* vrow = (const float4*)(var + ((size_t)(b * NT + idx)) * ND);
        float lsum = 0.f, asum = 0.f;
#pragma unroll
        for (int it = 0; it < 4; ++it) {
            int f = lane + it * 32;
            float4 m4 = mrow[f], v4 = vrow[f];
            v4.x += FEPS; v4.y += FEPS; v4.z += FEPS; v4.w += FEPS;
            float4 r4 = make_float4(1.f / v4.x, 1.f / v4.y, 1.f / v4.z, 1.f / v4.w);
            float4 s4 = make_float4(m4.x * r4.x, m4.y * r4.y, m4.z * r4.z, m4.w * r4.w);
            ((float4*)(r_q + j * ND))[f] = r4;
            ((float4*)(s_q + j * ND))[f] = s4;
            lsum += __log2f(v4.x) + __log2f(v4.y) + __log2f(v4.z) + __log2f(v4.w);
            asum += m4.x * s4.x + m4.y * s4.y + m4.z * s4.z + m4.w * s4.w;
        }
        float red = warp_sum(asum + LN2F * lsum);
        if (lane == 0) Dq[j] = 0.5f * red;
    }

    // stage p rows in registers
    unsigned long long up[4][8], wp[4][8];
    float halfLp[4];
#pragma unroll
    for (int rr = 0; rr < 4; ++rr) {
        const int pset = 2 + (rr >> 1);
        const int idx = g_idx[b][pset][warp * 2 + (rr & 1)];
        const float4* mrow = (const float4*)(mu  + ((size_t)(b * NT + idx)) * ND);
        const float4* vrow = (const float4*)(var + ((size_t)(b * NT + idx)) * ND);
        float lsum = 0.f;
#pragma unroll
        for (int it = 0; it < 4; ++it) {
            int f = lane + it * 32;
            float4 m4 = mrow[f], v4 = vrow[f];
            v4.x += FEPS; v4.y += FEPS; v4.z += FEPS; v4.w += FEPS;
            up[rr][2 * it]     = pk2(m4.x * m4.x + v4.x, m4.y * m4.y + v4.y);
            up[rr][2 * it + 1] = pk2(m4.z * m4.z + v4.z, m4.w * m4.w + v4.w);
            wp[rr][2 * it]     = pk2(-2.f * m4.x, -2.f * m4.y);
            wp[rr][2 * it + 1] = pk2(-2.f * m4.z, -2.f * m4.w);
            lsum += __log2f(v4.x) + __log2f(v4.y) + __log2f(v4.z) + __log2f(v4.w);
        }
        lsum = warp_sum(lsum);
        halfLp[rr] = 0.5f * LN2F * __shfl_sync(0xffffffffu, lsum, 0);
    }
    __syncthreads();

    float accinv[4] = {0.f, 0.f, 0.f, 0.f};
    for (int j = 0; j < 20; ++j) {
        const ulonglong2* rq2 = (const ulonglong2*)(r_q + j * ND);
        const ulonglong2* sq2 = (const ulonglong2*)(s_q + j * ND);
        unsigned long long au[4] = {0, 0, 0, 0}, aw[4] = {0, 0, 0, 0};
#pragma unroll
        for (int it = 0; it < 4; ++it) {
            ulonglong2 r2 = rq2[lane + it * 32];
            ulonglong2 s2 = sq2[lane + it * 32];
#pragma unroll
            for (int rr = 0; rr < 4; ++rr) {
                au[rr] = ffma2(up[rr][2 * it],     r2.x, au[rr]);
                au[rr] = ffma2(up[rr][2 * it + 1], r2.y, au[rr]);
                aw[rr] = ffma2(wp[rr][2 * it],     s2.x, aw[rr]);
                aw[rr] = ffma2(wp[rr][2 * it + 1], s2.y, aw[rr]);
            }
        }
#pragma unroll
        for (int rr = 0; rr < 4; ++rr) {
            float2 a2 = upk2(au[rr]), b2 = upk2(aw[rr]);
            float red = warp_sum(a2.x + a2.y + b2.x + b2.y);
            if (lane == 0) {
                float dist = 0.5f * red + Dq[j] - halfLp[rr] - 0.5f * (float)ND;
                accinv[rr] += 1.f / (dist + 1.f);
            }
        }
    }
    if (lane == 0) {
        const int c_act = qs;                  // 0: pos_act, 1: neg_act
        const int c_bkg = (qs == 0) ? 3 : 2;   // 3: neg_bkg, 2: pos_bkg
        atomicAdd(&g_kl[b][c_act], accinv[0] + accinv[1]);
        atomicAdd(&g_kl[b][c_bkg], accinv[2] + accinv[3]);
    }
}

// warp-per-row cosine similarity + global mean (double accumulation)
__global__ void __launch_bounds__(256) k_distill(const float* __restrict__ mu,
                                                 const float* __restrict__ mc) {
    const int lane = threadIdx.x & 31;
    const int wib  = threadIdx.x >> 5;
    const int gw   = blockIdx.x * 8 + wib;
    const int nw   = gridDim.x * 8;
    double local = 0.0;
    for (int row = gw; row < NB * NT; row += nw) {
        const float4* a = (const float4*)(mu + (size_t)row * ND);
        const float4* c = (const float4*)(mc + (size_t)row * ND);
        float dot = 0.f, n1 = 0.f, n2 = 0.f;
#pragma unroll
        for (int it = 0; it < 4; ++it) {
            float4 x = a[lane + it * 32];
            float4 y = c[lane + it * 32];
            dot += x.x * y.x + x.y * y.y + x.z * y.z + x.w * y.w;
            n1  += x.x * x.x + x.y * x.y + x.z * x.z + x.w * x.w;
            n2  += y.x * y.x + y.y * y.y + y.z * y.z + y.w * y.w;
        }
#pragma unroll
        for (int o = 16; o; o >>= 1) {
            dot += __shfl_down_sync(0xffffffffu, dot, o);
            n1  += __shfl_down_sync(0xffffffffu, n1, o);
            n2  += __shfl_down_sync(0xffffffffu, n2, o);
        }
        if (lane == 0) {
            float sim = dot / (fmaxf(sqrtf(n1), 1e-12f) * fmaxf(sqrtf(n2), 1e-12f));
            local += (double)((sim + 1.f) * 0.5f);
        }
    }
    __shared__ double bs[8];
    if (lane == 0) bs[wib] = local;
    __syncthreads();
    if (threadIdx.x == 0) {
        double s = 0.0;
        for (int w = 0; w < 8; ++w) s += bs[w];
        atomicAdd(&g_distill_sum, s);
    }
}

// single block: ortho (Frobenius norm) then final scalar assembly
__global__ void __launch_bounds__(512) k_fin(const float* __restrict__ tf,
                                             float* __restrict__ out, int out_size) {
    __shared__ float e[NC * ND];
    __shared__ float partial[16];
    const int tid = threadIdx.x;
    const int warp = tid >> 5, lane = tid & 31;
    for (int i = tid; i < NC * ND; i += 512) e[i] = tf[i];
    __syncthreads();
    for (int r = warp; r < NC; r += 16) {
        float s = 0.f;
        for (int d = lane; d < ND; d += 32) { float v = e[r * ND + d]; s += v * v; }
        s = warp_sum(s);
        float inv = 1.f / fmaxf(sqrtf(__shfl_sync(0xffffffffu, s, 0)), 1e-12f);
        for (int d = lane; d < ND; d += 32) e[r * ND + d] *= inv;
    }
    __syncthreads();
    float acc = 0.f;
    for (int p = warp; p < NC * NC; p += 16) {
        int i = p / NC, j = p % NC;
        float s = 0.f;
        for (int d = lane; d < ND; d += 32) s += e[i * ND + d] * e[j * ND + d];
        s = warp_sum(s);
        if (lane == 0) {
            float m = s - ((i == j) ? 1.f : 0.f);
            acc += m * m;
        }
    }
    if (lane == 0) partial[warp] = acc;
    __syncthreads();
    if (tid == 0) {
        float s = 0.f;
        for (int w = 0; w < 16; ++w) s += partial[w];
        float ortho = sqrtf(s);
        float distill = -logf((float)(g_distill_sum / (double)(NB * NT)));
        const float inv_pairs = 1.f / (float)(KH * KE);
        float act = 0.f, bkg = 0.f;
        for (int b = 0; b < NB; ++b) {
            act += -(logf(g_kl[b][0] * inv_pairs) + logf(1.f - g_kl[b][1] * inv_pairs));
            bkg += -(logf(g_kl[b][2] * inv_pairs) + logf(1.f - g_kl[b][3] * inv_pairs));
        }
        act /= (float)NB;
        bkg /= (float)NB;
        float total = distill + act + bkg + ortho;
        float vals[5] = {total, distill, act, bkg, ortho};
        for (int i = 0; i < out_size && i < 5; ++i) out[i] = vals[i];
    }
}

// ---------------- launch ----------------
extern "C" void kernel_launch(void* const* d_in, const int* in_sizes, int n_in,
                              void* d_out, int out_size) {
    const float* attn      = (const float*)d_in[0];
    const float* mu        = (const float*)d_in[1];
    const float* var       = (const float*)d_in[2];
    const float* mu_clip   = (const float*)d_in[3];
    const float* text_feat = (const float*)d_in[4];
    const float* dmask     = (const float*)d_in[5];
    float* out = (float*)d_out;

    const int kl_smem = 2 * 20 * ND * (int)sizeof(float);   // 80 KB
    cudaFuncSetAttribute(k_kl, cudaFuncAttributeMaxDynamicSharedMemorySize, kl_smem);

    k_prep<<<NB, 256>>>(attn);
    k_topk<<<dim3(4, NB), 256>>>(attn, dmask);
    k_kl<<<dim3(4, NB), 320, kl_smem>>>(mu, var);
    k_distill<<<2048, 256>>>(mu, mu_clip);
    k_fin<<<1, 512>>>(text_feat, out, out_size);
}

// round 4
// speedup vs baseline: 1.2277x; 1.2277x over previous
#include <cuda_runtime.h>
#include <math.h>

#define NB 16
#define NT 2048
#define ND 512
#define NC 20
#define KE 40
#define KH 20
#define FEPS 1e-5f
#define LN2F 0.69314718055994531f

// ---------------- scratch (write-only slots, no zeroing needed) ----------------
__device__ int    g_idx[NB][4][KE];     // 0=easy_act,1=easy_bkg,2=hard_act,3=hard_bkg
__device__ float  g_klp[NB][8][2];      // per (b, qchunk): [0]=vs hard_act, [1]=vs hard_bkg
__device__ double g_dpart[2048];        // distill per-block partials

// ---------------- helpers ----------------
__device__ __forceinline__ float warp_sum(float v) {
#pragma unroll
    for (int o = 16; o; o >>= 1) v += __shfl_down_sync(0xffffffffu, v, o);
    return v;
}
__device__ __forceinline__ float warp_max(float v) {
#pragma unroll
    for (int o = 16; o; o >>= 1) v = fmaxf(v, __shfl_down_sync(0xffffffffu, v, o));
    return v;
}
__device__ __forceinline__ double warp_dsum(double v) {
#pragma unroll
    for (int o = 16; o; o >>= 1) v += __shfl_down_sync(0xffffffffu, v, o);
    return v;
}
__device__ __forceinline__ unsigned long long pk2(float lo, float hi) {
    unsigned long long r;
    asm("mov.b64 %0, {%1, %2};" : "=l"(r) : "f"(lo), "f"(hi));
    return r;
}
__device__ __forceinline__ float2 upk2(unsigned long long v) {
    float2 f;
    asm("mov.b64 {%0, %1}, %2;" : "=f"(f.x), "=f"(f.y) : "l"(v));
    return f;
}
__device__ __forceinline__ unsigned long long ffma2(unsigned long long a,
                                                   unsigned long long b,
                                                   unsigned long long c) {
    unsigned long long d;
    asm("fma.rn.f32x2 %0, %1, %2, %3;" : "=l"(d) : "l"(a), "l"(b), "l"(c));
    return d;
}

// Descending radix select: bit pattern of the value at rank k (0-indexed desc).
// All scores >= 0 so bit order == value order. Called uniformly by the block.
__device__ unsigned radix_select_desc(const float* sc, int n, int k,
                                      unsigned* hist, unsigned* shc) {
    const int tid = threadIdx.x, nthr = blockDim.x;
    unsigned prefix = 0, pmask = 0;
#pragma unroll
    for (int level = 0; level < 4; ++level) {
        const int shift = 24 - 8 * level;
        for (int i = tid; i < 256; i += nthr) hist[i] = 0;
        __syncthreads();
        for (int i = tid; i < n; i += nthr) {
            unsigned u = __float_as_uint(sc[i]);
            bool ok = ((u & pmask) == prefix);
            unsigned d = ok ? ((u >> shift) & 255u) : 0x100u;
            unsigned mm = __match_any_sync(0xffffffffu, d);
            if (ok && ((tid & 31) == __ffs(mm) - 1))
                atomicAdd(&hist[d], (unsigned)__popc(mm));
        }
        __syncthreads();
        if (tid < 32) {
            const int l = tid;
            unsigned c[8]; unsigned lsum = 0;
#pragma unroll
            for (int i = 0; i < 8; ++i) { c[i] = hist[l * 8 + i]; lsum += c[i]; }
            unsigned v = lsum;
#pragma unroll
            for (int off = 1; off < 32; off <<= 1) {
                unsigned t = __shfl_down_sync(0xffffffffu, v, off);
                if (l + off < 32) v += t;
            }
            unsigned cum = v - lsum;          // elements in higher bins
            int found = -1; unsigned nk = 0;
#pragma unroll
            for (int i = 7; i >= 0; --i) {
                if (found < 0 && (unsigned)k >= cum && (unsigned)k < cum + c[i]) {
                    found = l * 8 + i; nk = (unsigned)k - cum;
                }
                cum += c[i];
            }
            if (found >= 0) { shc[0] = (unsigned)found; shc[1] = nk; }
        }
        __syncthreads();
        prefix |= shc[0] << shift;
        pmask  |= 0xFFu << shift;
        k = (int)shc[1];
        __syncthreads();
    }
    return prefix;
}

// ---------------- kernels ----------------
// One block per (score_set s, batch b): self-contained (median computed locally
// for s>=2), emits top-K index set with exact top_k tie-break (lowest index).
__global__ void __launch_bounds__(512) k_topk(const float* __restrict__ attn,
                                              const float* __restrict__ dmask) {
    __shared__ float sa[NT];
    __shared__ float ss[NT];
    __shared__ unsigned char sab[NT];
    __shared__ unsigned hist[256];
    __shared__ unsigned shc[2];
    __shared__ unsigned bm[NT / 32];
    __shared__ unsigned pfx[NT / 32];
    __shared__ float red[16];
    __shared__ int s_cnt;
    __shared__ int s_cntGE;
    __shared__ float s_maxLess;
    const int s = blockIdx.x, b = blockIdx.y, tid = threadIdx.x;
    const int warp = tid >> 5, lane = tid & 31;

    float lmax = 0.f;
    for (int t = tid; t < NT; t += 512) {
        float v = attn[b * NT + t];
        sa[t] = v;
        lmax = fmaxf(lmax, v);
    }
    lmax = warp_max(lmax);
    if (lane == 0) red[warp] = lmax;
    if (tid == 0) { s_cntGE = 0; s_maxLess = 0.f; }
    __syncthreads();
    float amax = red[0];
#pragma unroll
    for (int w = 1; w < 16; ++w) amax = fmaxf(amax, red[w]);

    if (s >= 2) {
        // exact median: v1 = rank1023 via radix select; v2 = rank1024 via one pass
        unsigned v1u = radix_select_desc(sa, NT, 1023, hist, shc);
        const float v1 = __uint_as_float(v1u);
        int cnt = 0; float ml = 0.f;
        for (int t = tid; t < NT; t += 512) {
            float x = sa[t];
            if (x >= v1) ++cnt; else ml = fmaxf(ml, x);
        }
#pragma unroll
        for (int o = 16; o; o >>= 1) {
            cnt += __shfl_down_sync(0xffffffffu, cnt, o);
            ml = fmaxf(ml, __shfl_down_sync(0xffffffffu, ml, o));
        }
        if (lane == 0) {
            atomicAdd(&s_cntGE, cnt);
            atomicMax((int*)&s_maxLess, __float_as_int(ml));   // floats >= 0
        }
        __syncthreads();
        float v2 = (s_cntGE >= 1025) ? v1 : s_maxLess;
        float med = 0.5f * (v1 + v2);
        for (int t = tid; t < NT; t += 512) sab[t] = (sa[t] > med) ? 1 : 0;
        __syncthreads();
    }

    for (int t = tid; t < NT; t += 512) {
        float a = sa[t];
        float v;
        if (s == 0) v = a * dmask[b * NT + t];
        else if (s == 1) v = (amax - a) * dmask[b * NT + t];
        else {
            int bm3 = (t >= 3) ? (int)sab[t - 3] : 0;
            int bm2 = (t >= 2) ? (int)sab[t - 2] : 0;
            int bm1 = (t >= 1) ? (int)sab[t - 1] : 0;
            int b0  = (int)sab[t];
            int bp1 = (t + 1 < NT) ? (int)sab[t + 1] : 0;
            int bp2 = (t + 2 < NT) ? (int)sab[t + 2] : 0;
            int bp3 = (t + 3 < NT) ? (int)sab[t + 3] : 0;
            if (s == 2) {
                int er3 = bm1 & b0 & bp1;
                int er7 = er3 & bm3 & bm2 & bp2 & bp3;
                v = a * (float)(er3 & (er7 ^ 1));
            } else {
                int dl3 = bm1 | b0 | bp1;
                int dl7 = dl3 | bm3 | bm2 | bp2 | bp3;
                v = a * (float)(dl7 & (dl3 ^ 1));
            }
        }
        ss[t] = v;
    }
    if (tid == 0) s_cnt = 0;
    for (int i = tid; i < NT / 32; i += 512) bm[i] = 0;
    __syncthreads();
    const int K = (s < 2) ? KE : KH;
    unsigned vk = radix_select_desc(ss, NT, K - 1, hist, shc);
    const float fvk = __uint_as_float(vk);
    for (int t = tid; t < NT; t += 512) {
        float v = ss[t];
        if (v > fvk) {
            int p = atomicAdd(&s_cnt, 1);
            g_idx[b][s][p] = t;
        } else if (v == fvk) {
            atomicOr(&bm[t >> 5], 1u << (t & 31));
        }
    }
    __syncthreads();
    if (tid < 32) {
        const int l = tid;
        unsigned p0 = __popc(bm[2 * l]), p1 = __popc(bm[2 * l + 1]);
        unsigned ls = p0 + p1, v = ls;
#pragma unroll
        for (int off = 1; off < 32; off <<= 1) {
            unsigned t2 = __shfl_up_sync(0xffffffffu, v, off);
            if (l >= off) v += t2;
        }
        unsigned excl = v - ls;
        pfx[2 * l] = excl;
        pfx[2 * l + 1] = excl + p0;
    }
    __syncthreads();
    const int base = s_cnt;
    const int m = K - base;
    for (int t = tid; t < NT; t += 512) {
        if (ss[t] == fvk) {
            int r = (int)(pfx[t >> 5] + __popc(bm[t >> 5] & ((1u << (t & 31)) - 1u)));
            if (r < m) g_idx[b][s][base + r] = t;
        }
    }
}

// grid (8, NB): blockIdx.x = qs*4 + qquarter. 640 threads = 20 warps.
// Warp w holds p-rows hard_act[w] (rr=0) and hard_bkg[w] (rr=1) in registers
// (u = mu^2+cov, w = -2mu, packed f32x2). q quarter (10 rows: r=1/cov, s=mu*r)
// staged in 40KB smem. dist = 0.5*(sum u*r + w*s) + Dq - 0.5*Lp - D/2.
__global__ void __launch_bounds__(640, 1) k_kl(const float* __restrict__ mu,
                                               const float* __restrict__ var) {
    extern __shared__ float sm[];
    float* r_q = sm;              // [10][ND]
    float* s_q = sm + 10 * ND;    // [10][ND]
    __shared__ float Dq[10];
    __shared__ float sAct[20], sBkg[20];
    const int qs = blockIdx.x >> 2;
    const int qq = blockIdx.x & 3;
    const int b  = blockIdx.y;
    const int warp = threadIdx.x >> 5;   // 0..19
    const int lane = threadIdx.x & 31;

    // stage p rows in registers (all warps)
    unsigned long long up[2][8], wp[2][8];
    float halfLp[2];
#pragma unroll
    for (int rr = 0; rr < 2; ++rr) {
        const int idx = g_idx[b][2 + rr][warp];
        const float4* mrow = (const float4*)(mu  + ((size_t)(b * NT + idx)) * ND);
        const float4* vrow = (const float4*)(var + ((size_t)(b * NT + idx)) * ND);
        float lsum = 0.f;
#pragma unroll
        for (int it = 0; it < 4; ++it) {
            int f = lane + it * 32;
            float4 m4 = mrow[f], v4 = vrow[f];
            v4.x += FEPS; v4.y += FEPS; v4.z += FEPS; v4.w += FEPS;
            up[rr][2 * it]     = pk2(m4.x * m4.x + v4.x, m4.y * m4.y + v4.y);
            up[rr][2 * it + 1] = pk2(m4.z * m4.z + v4.z, m4.w * m4.w + v4.w);
            wp[rr][2 * it]     = pk2(-2.f * m4.x, -2.f * m4.y);
            wp[rr][2 * it + 1] = pk2(-2.f * m4.z, -2.f * m4.w);
            lsum += __log2f(v4.x) + __log2f(v4.y) + __log2f(v4.z) + __log2f(v4.w);
        }
        lsum = warp_sum(lsum);
        halfLp[rr] = 0.5f * LN2F * __shfl_sync(0xffffffffu, lsum, 0);
    }

    // stage q rows (warps 0..9, one row each)
    if (warp < 10) {
        const int j = warp;
        const int idx = g_idx[b][qs][qq * 10 + j];
        const float4* mrow = (const float4*)(mu  + ((size_t)(b * NT + idx)) * ND);
        const float4* vrow = (const float4*)(var + ((size_t)(b * NT + idx)) * ND);
        float lsum = 0.f, asum = 0.f;
#pragma unroll
        for (int it = 0; it < 4; ++it) {
            int f = lane + it * 32;
            float4 m4 = mrow[f], v4 = vrow[f];
            v4.x += FEPS; v4.y += FEPS; v4.z += FEPS; v4.w += FEPS;
            float4 r4 = make_float4(1.f / v4.x, 1.f / v4.y, 1.f / v4.z, 1.f / v4.w);
            float4 s4 = make_float4(m4.x * r4.x, m4.y * r4.y, m4.z * r4.z, m4.w * r4.w);
            ((float4*)(r_q + j * ND))[f] = r4;
            ((float4*)(s_q + j * ND))[f] = s4;
            lsum += __log2f(v4.x) + __log2f(v4.y) + __log2f(v4.z) + __log2f(v4.w);
            asum += m4.x * s4.x + m4.y * s4.y + m4.z * s4.z + m4.w * s4.w;
        }
        float red2 = warp_sum(asum + LN2F * lsum);
        if (lane == 0) Dq[j] = 0.5f * red2;
    }
    __syncthreads();

    float accinv[2] = {0.f, 0.f};
    for (int j = 0; j < 10; ++j) {
        const ulonglong2* rq2 = (const ulonglong2*)(r_q + j * ND);
        const ulonglong2* sq2 = (const ulonglong2*)(s_q + j * ND);
        unsigned long long acc[2] = {0, 0};
#pragma unroll
        for (int it = 0; it < 4; ++it) {
            ulonglong2 r2 = rq2[lane + it * 32];
            ulonglong2 s2 = sq2[lane + it * 32];
#pragma unroll
            for (int rr = 0; rr < 2; ++rr) {
                acc[rr] = ffma2(up[rr][2 * it],     r2.x, acc[rr]);
                acc[rr] = ffma2(up[rr][2 * it + 1], r2.y, acc[rr]);
                acc[rr] = ffma2(wp[rr][2 * it],     s2.x, acc[rr]);
                acc[rr] = ffma2(wp[rr][2 * it + 1], s2.y, acc[rr]);
            }
        }
#pragma unroll
        for (int rr = 0; rr < 2; ++rr) {
            float2 a2 = upk2(acc[rr]);
            float red2 = warp_sum(a2.x + a2.y);
            if (lane == 0) {
                float dist = 0.5f * red2 + Dq[j] - halfLp[rr] - 0.5f * (float)ND;
                accinv[rr] += 1.f / (dist + 1.f);
            }
        }
    }
    if (lane == 0) { sAct[warp] = accinv[0]; sBkg[warp] = accinv[1]; }
    __syncthreads();
    if (warp == 0) {
        float va = (lane < 20) ? sAct[lane] : 0.f;
        float vb = (lane < 20) ? sBkg[lane] : 0.f;
        va = warp_sum(va);
        vb = warp_sum(vb);
        if (lane == 0) {
            g_klp[b][blockIdx.x][0] = va;
            g_klp[b][blockIdx.x][1] = vb;
        }
    }
}

// warp handles 2 rows (r, r+16384): 16 independent float4 load chains for MLP.
__global__ void __launch_bounds__(256) k_distill(const float* __restrict__ mu,
                                                 const float* __restrict__ mc) {
    const int lane = threadIdx.x & 31;
    const int wib  = threadIdx.x >> 5;
    const int gw   = blockIdx.x * 8 + wib;        // 0..16383
    const size_t r0 = (size_t)gw * ND;
    const size_t r1 = (size_t)(gw + 16384) * ND;
    const float4* a0 = (const float4*)(mu + r0);
    const float4* c0 = (const float4*)(mc + r0);
    const float4* a1 = (const float4*)(mu + r1);
    const float4* c1 = (const float4*)(mc + r1);
    float d0 = 0.f, p0 = 0.f, q0 = 0.f;
    float d1 = 0.f, p1 = 0.f, q1 = 0.f;
#pragma unroll
    for (int it = 0; it < 4; ++it) {
        int f = lane + it * 32;
        float4 x0 = a0[f], y0 = c0[f], x1 = a1[f], y1 = c1[f];
        d0 += x0.x * y0.x + x0.y * y0.y + x0.z * y0.z + x0.w * y0.w;
        p0 += x0.x * x0.x + x0.y * x0.y + x0.z * x0.z + x0.w * x0.w;
        q0 += y0.x * y0.x + y0.y * y0.y + y0.z * y0.z + y0.w * y0.w;
        d1 += x1.x * y1.x + x1.y * y1.y + x1.z * y1.z + x1.w * y1.w;
        p1 += x1.x * x1.x + x1.y * x1.y + x1.z * x1.z + x1.w * x1.w;
        q1 += y1.x * y1.x + y1.y * y1.y + y1.z * y1.z + y1.w * y1.w;
    }
#pragma unroll
    for (int o = 16; o; o >>= 1) {
        d0 += __shfl_down_sync(0xffffffffu, d0, o);
        p0 += __shfl_down_sync(0xffffffffu, p0, o);
        q0 += __shfl_down_sync(0xffffffffu, q0, o);
        d1 += __shfl_down_sync(0xffffffffu, d1, o);
        p1 += __shfl_down_sync(0xffffffffu, p1, o);
        q1 += __shfl_down_sync(0xffffffffu, q1, o);
    }
    __shared__ double bs[8];
    if (lane == 0) {
        float s0 = d0 / (fmaxf(sqrtf(p0), 1e-12f) * fmaxf(sqrtf(q0), 1e-12f));
        float s1 = d1 / (fmaxf(sqrtf(p1), 1e-12f) * fmaxf(sqrtf(q1), 1e-12f));
        bs[wib] = (double)((s0 + 1.f) * 0.5f) + (double)((s1 + 1.f) * 0.5f);
    }
    __syncthreads();
    if (threadIdx.x == 0) {
        double s = 0.0;
        for (int w = 0; w < 8; ++w) s += bs[w];
        g_dpart[blockIdx.x] = s;
    }
}

// single block: distill partial reduce, ortho, final scalar assembly
__global__ void __launch_bounds__(512) k_fin(const float* __restrict__ tf,
                                             float* __restrict__ out, int out_size) {
    __shared__ float e[NC * ND];
    __shared__ float partial[16];
    __shared__ double dpartial[16];
    const int tid = threadIdx.x;
    const int warp = tid >> 5, lane = tid & 31;

    // distill sum (2048 doubles)
    double dl = 0.0;
#pragma unroll
    for (int i = 0; i < 4; ++i) dl += g_dpart[tid + i * 512];
    dl = warp_dsum(dl);
    if (lane == 0) dpartial[warp] = dl;

    for (int i = tid; i < NC * ND; i += 512) e[i] = tf[i];
    __syncthreads();
    for (int r = warp; r < NC; r += 16) {
        float s = 0.f;
        for (int d = lane; d < ND; d += 32) { float v = e[r * ND + d]; s += v * v; }
        s = warp_sum(s);
        float inv = 1.f / fmaxf(sqrtf(__shfl_sync(0xffffffffu, s, 0)), 1e-12f);
        for (int d = lane; d < ND; d += 32) e[r * ND + d] *= inv;
    }
    __syncthreads();
    float acc = 0.f;
    for (int p = warp; p < NC * NC; p += 16) {
        int i = p / NC, j = p % NC;
        float s = 0.f;
        for (int d = lane; d < ND; d += 32) s += e[i * ND + d] * e[j * ND + d];
        s = warp_sum(s);
        if (lane == 0) {
            float m = s - ((i == j) ? 1.f : 0.f);
            acc += m * m;
        }
    }
    if (lane == 0) partial[warp] = acc;
    __syncthreads();
    if (tid == 0) {
        float s = 0.f;
        for (int w = 0; w < 16; ++w) s += partial[w];
        float ortho = sqrtf(s);
        double ds = 0.0;
        for (int w = 0; w < 16; ++w) ds += dpartial[w];
        float distill = -logf((float)(ds / (double)(NB * NT)));
        const float inv_pairs = 1.f / (float)(KH * KE);
        float act = 0.f, bkg = 0.f;
        for (int b = 0; b < NB; ++b) {
            float c0 = 0.f, c1 = 0.f, c2 = 0.f, c3 = 0.f;
            for (int x = 0; x < 4; ++x) { c0 += g_klp[b][x][0]; c3 += g_klp[b][x][1]; }
            for (int x = 4; x < 8; ++x) { c1 += g_klp[b][x][0]; c2 += g_klp[b][x][1]; }
            act += -(logf(c0 * inv_pairs) + logf(1.f - c1 * inv_pairs));
            bkg += -(logf(c2 * inv_pairs) + logf(1.f - c3 * inv_pairs));
        }
        act /= (float)NB;
        bkg /= (float)NB;
        float total = distill + act + bkg + ortho;
        float vals[5] = {total, distill, act, bkg, ortho};
        for (int i = 0; i < out_size && i < 5; ++i) out[i] = vals[i];
    }
}

// ---------------- launch (fork/join: distill overlaps the selection chain) ----
extern "C" void kernel_launch(void* const* d_in, const int* in_sizes, int n_in,
                              void* d_out, int out_size) {
    const float* attn      = (const float*)d_in[0];
    const float* mu        = (const float*)d_in[1];
    const float* var       = (const float*)d_in[2];
    const float* mu_clip   = (const float*)d_in[3];
    const float* text_feat = (const float*)d_in[4];
    const float* dmask     = (const float*)d_in[5];
    float* out = (float*)d_out;

    static cudaStream_t sB = nullptr;
    static cudaEvent_t evFork = nullptr, evJoin = nullptr;
    if (sB == nullptr) {
        cudaStreamCreateWithFlags(&sB, cudaStreamNonBlocking);
        cudaEventCreateWithFlags(&evFork, cudaEventDisableTiming);
        cudaEventCreateWithFlags(&evJoin, cudaEventDisableTiming);
    }

    const int kl_smem = 2 * 10 * ND * (int)sizeof(float);   // 40 KB

    // fork: distill on sB
    cudaEventRecord(evFork, 0);
    cudaStreamWaitEvent(sB, evFork, 0);
    k_distill<<<2048, 256, 0, sB>>>(mu, mu_clip);
    cudaEventRecord(evJoin, sB);

    // chain A on main stream
    k_topk<<<dim3(4, NB), 512>>>(attn, dmask);
    k_kl<<<dim3(8, NB), 640, kl_smem>>>(mu, var);

    // join + finalize
    cudaStreamWaitEvent(0, evJoin, 0);
    k_fin<<<1, 512>>>(text_feat, out, out_size);
}

// round 5
// speedup vs baseline: 1.4743x; 1.2008x over previous
#include <cuda_runtime.h>
#include <math.h>

#define NB 16
#define NT 2048
#define ND 512
#define NC 20
#define KE 40
#define KH 20
#define FEPS 1e-5f
#define LN2F 0.69314718055994531f

// ---------------- scratch (write-only slots, no zeroing needed) ----------------
__device__ int    g_idx[NB][4][KE];     // 0=easy_act,1=easy_bkg,2=hard_act,3=hard_bkg
__device__ float  g_klp[NB][8][2];      // per (b, qchunk): [0]=vs hard_act, [1]=vs hard_bkg
__device__ double g_dpart[1024];        // distill per-block partials
__device__ float  g_opart[NC];          // ortho per-row partial sums of squares

// ---------------- helpers ----------------
__device__ __forceinline__ float warp_sum(float v) {
#pragma unroll
    for (int o = 16; o; o >>= 1) v += __shfl_down_sync(0xffffffffu, v, o);
    return v;
}
__device__ __forceinline__ float warp_max(float v) {
#pragma unroll
    for (int o = 16; o; o >>= 1) v = fmaxf(v, __shfl_down_sync(0xffffffffu, v, o));
    return v;
}
__device__ __forceinline__ double warp_dsum(double v) {
#pragma unroll
    for (int o = 16; o; o >>= 1) v += __shfl_down_sync(0xffffffffu, v, o);
    return v;
}
__device__ __forceinline__ unsigned long long pk2(float lo, float hi) {
    unsigned long long r;
    asm("mov.b64 %0, {%1, %2};" : "=l"(r) : "f"(lo), "f"(hi));
    return r;
}
__device__ __forceinline__ float2 upk2(unsigned long long v) {
    float2 f;
    asm("mov.b64 {%0, %1}, %2;" : "=f"(f.x), "=f"(f.y) : "l"(v));
    return f;
}
__device__ __forceinline__ unsigned long long ffma2(unsigned long long a,
                                                   unsigned long long b,
                                                   unsigned long long c) {
    unsigned long long d;
    asm("fma.rn.f32x2 %0, %1, %2, %3;" : "=l"(d) : "l"(a), "l"(b), "l"(c));
    return d;
}

// Descending radix select: bit pattern of the value at rank k (0-indexed desc).
// All scores >= 0 so bit order == value order. Called uniformly by the block.
__device__ unsigned radix_select_desc(const float* sc, int n, int k,
                                      unsigned* hist, unsigned* shc) {
    const int tid = threadIdx.x, nthr = blockDim.x;
    unsigned prefix = 0, pmask = 0;
#pragma unroll
    for (int level = 0; level < 4; ++level) {
        const int shift = 24 - 8 * level;
        for (int i = tid; i < 256; i += nthr) hist[i] = 0;
        __syncthreads();
        for (int i = tid; i < n; i += nthr) {
            unsigned u = __float_as_uint(sc[i]);
            bool ok = ((u & pmask) == prefix);
            unsigned d = ok ? ((u >> shift) & 255u) : 0x100u;
            unsigned mm = __match_any_sync(0xffffffffu, d);
            if (ok && ((tid & 31) == __ffs(mm) - 1))
                atomicAdd(&hist[d], (unsigned)__popc(mm));
        }
        __syncthreads();
        if (tid < 32) {
            const int l = tid;
            unsigned c[8]; unsigned lsum = 0;
#pragma unroll
            for (int i = 0; i < 8; ++i) { c[i] = hist[l * 8 + i]; lsum += c[i]; }
            unsigned v = lsum;
#pragma unroll
            for (int off = 1; off < 32; off <<= 1) {
                unsigned t = __shfl_down_sync(0xffffffffu, v, off);
                if (l + off < 32) v += t;
            }
            unsigned cum = v - lsum;          // elements in higher bins
            int found = -1; unsigned nk = 0;
#pragma unroll
            for (int i = 7; i >= 0; --i) {
                if (found < 0 && (unsigned)k >= cum && (unsigned)k < cum + c[i]) {
                    found = l * 8 + i; nk = (unsigned)k - cum;
                }
                cum += c[i];
            }
            if (found >= 0) { shc[0] = (unsigned)found; shc[1] = nk; }
        }
        __syncthreads();
        prefix |= shc[0] << shift;
        pmask  |= 0xFFu << shift;
        k = (int)shc[1];
        __syncthreads();
    }
    return prefix;
}

// ---------------- kernels ----------------
// One block per (score_set s, batch b): self-contained (median computed locally
// for s>=2), emits top-K index set with exact top_k tie-break (lowest index).
__global__ void __launch_bounds__(512) k_topk(const float* __restrict__ attn,
                                              const float* __restrict__ dmask) {
    __shared__ float sa[NT];
    __shared__ float ss[NT];
    __shared__ unsigned char sab[NT];
    __shared__ unsigned hist[256];
    __shared__ unsigned shc[2];
    __shared__ unsigned bm[NT / 32];
    __shared__ unsigned pfx[NT / 32];
    __shared__ float red[16];
    __shared__ int s_cnt;
    __shared__ int s_cntGE;
    __shared__ float s_maxLess;
    const int s = blockIdx.x, b = blockIdx.y, tid = threadIdx.x;
    const int warp = tid >> 5, lane = tid & 31;

    float lmax = 0.f;
    for (int t = tid; t < NT; t += 512) {
        float v = attn[b * NT + t];
        sa[t] = v;
        lmax = fmaxf(lmax, v);
    }
    lmax = warp_max(lmax);
    if (lane == 0) red[warp] = lmax;
    if (tid == 0) { s_cntGE = 0; s_maxLess = 0.f; }
    __syncthreads();
    float amax = red[0];
#pragma unroll
    for (int w = 1; w < 16; ++w) amax = fmaxf(amax, red[w]);

    if (s >= 2) {
        // exact median: v1 = rank1023 via radix select; v2 = rank1024 via one pass
        unsigned v1u = radix_select_desc(sa, NT, 1023, hist, shc);
        const float v1 = __uint_as_float(v1u);
        int cnt = 0; float ml = 0.f;
        for (int t = tid; t < NT; t += 512) {
            float x = sa[t];
            if (x >= v1) ++cnt; else ml = fmaxf(ml, x);
        }
#pragma unroll
        for (int o = 16; o; o >>= 1) {
            cnt += __shfl_down_sync(0xffffffffu, cnt, o);
            ml = fmaxf(ml, __shfl_down_sync(0xffffffffu, ml, o));
        }
        if (lane == 0) {
            atomicAdd(&s_cntGE, cnt);
            atomicMax((int*)&s_maxLess, __float_as_int(ml));   // floats >= 0
        }
        __syncthreads();
        float v2 = (s_cntGE >= 1025) ? v1 : s_maxLess;
        float med = 0.5f * (v1 + v2);
        for (int t = tid; t < NT; t += 512) sab[t] = (sa[t] > med) ? 1 : 0;
        __syncthreads();
    }

    for (int t = tid; t < NT; t += 512) {
        float a = sa[t];
        float v;
        if (s == 0) v = a * dmask[b * NT + t];
        else if (s == 1) v = (amax - a) * dmask[b * NT + t];
        else {
            int bm3 = (t >= 3) ? (int)sab[t - 3] : 0;
            int bm2 = (t >= 2) ? (int)sab[t - 2] : 0;
            int bm1 = (t >= 1) ? (int)sab[t - 1] : 0;
            int b0  = (int)sab[t];
            int bp1 = (t + 1 < NT) ? (int)sab[t + 1] : 0;
            int bp2 = (t + 2 < NT) ? (int)sab[t + 2] : 0;
            int bp3 = (t + 3 < NT) ? (int)sab[t + 3] : 0;
            if (s == 2) {
                int er3 = bm1 & b0 & bp1;
                int er7 = er3 & bm3 & bm2 & bp2 & bp3;
                v = a * (float)(er3 & (er7 ^ 1));
            } else {
                int dl3 = bm1 | b0 | bp1;
                int dl7 = dl3 | bm3 | bm2 | bp2 | bp3;
                v = a * (float)(dl7 & (dl3 ^ 1));
            }
        }
        ss[t] = v;
    }
    if (tid == 0) s_cnt = 0;
    for (int i = tid; i < NT / 32; i += 512) bm[i] = 0;
    __syncthreads();
    const int K = (s < 2) ? KE : KH;
    unsigned vk = radix_select_desc(ss, NT, K - 1, hist, shc);
    const float fvk = __uint_as_float(vk);
    for (int t = tid; t < NT; t += 512) {
        float v = ss[t];
        if (v > fvk) {
            int p = atomicAdd(&s_cnt, 1);
            g_idx[b][s][p] = t;
        } else if (v == fvk) {
            atomicOr(&bm[t >> 5], 1u << (t & 31));
        }
    }
    __syncthreads();
    if (tid < 32) {
        const int l = tid;
        unsigned p0 = __popc(bm[2 * l]), p1 = __popc(bm[2 * l + 1]);
        unsigned ls = p0 + p1, v = ls;
#pragma unroll
        for (int off = 1; off < 32; off <<= 1) {
            unsigned t2 = __shfl_up_sync(0xffffffffu, v, off);
            if (l >= off) v += t2;
        }
        unsigned excl = v - ls;
        pfx[2 * l] = excl;
        pfx[2 * l + 1] = excl + p0;
    }
    __syncthreads();
    const int base = s_cnt;
    const int m = K - base;
    for (int t = tid; t < NT; t += 512) {
        if (ss[t] == fvk) {
            int r = (int)(pfx[t >> 5] + __popc(bm[t >> 5] & ((1u << (t & 31)) - 1u)));
            if (r < m) g_idx[b][s][base + r] = t;
        }
    }
}

// grid (8, NB): blockIdx.x = qs*4 + qquarter. 640 threads = 20 warps.
__global__ void __launch_bounds__(640, 1) k_kl(const float* __restrict__ mu,
                                               const float* __restrict__ var) {
    extern __shared__ float sm[];
    float* r_q = sm;              // [10][ND]
    float* s_q = sm + 10 * ND;    // [10][ND]
    __shared__ float Dq[10];
    __shared__ float sAct[20], sBkg[20];
    const int qs = blockIdx.x >> 2;
    const int qq = blockIdx.x & 3;
    const int b  = blockIdx.y;
    const int warp = threadIdx.x >> 5;   // 0..19
    const int lane = threadIdx.x & 31;

    // stage p rows in registers (all warps)
    unsigned long long up[2][8], wp[2][8];
    float halfLp[2];
#pragma unroll
    for (int rr = 0; rr < 2; ++rr) {
        const int idx = g_idx[b][2 + rr][warp];
        const float4* mrow = (const float4*)(mu  + ((size_t)(b * NT + idx)) * ND);
        const float4* vrow = (const float4*)(var + ((size_t)(b * NT + idx)) * ND);
        float lsum = 0.f;
#pragma unroll
        for (int it = 0; it < 4; ++it) {
            int f = lane + it * 32;
            float4 m4 = mrow[f], v4 = vrow[f];
            v4.x += FEPS; v4.y += FEPS; v4.z += FEPS; v4.w += FEPS;
            up[rr][2 * it]     = pk2(m4.x * m4.x + v4.x, m4.y * m4.y + v4.y);
            up[rr][2 * it + 1] = pk2(m4.z * m4.z + v4.z, m4.w * m4.w + v4.w);
            wp[rr][2 * it]     = pk2(-2.f * m4.x, -2.f * m4.y);
            wp[rr][2 * it + 1] = pk2(-2.f * m4.z, -2.f * m4.w);
            lsum += __log2f(v4.x) + __log2f(v4.y) + __log2f(v4.z) + __log2f(v4.w);
        }
        lsum = warp_sum(lsum);
        halfLp[rr] = 0.5f * LN2F * __shfl_sync(0xffffffffu, lsum, 0);
    }

    // stage q rows (warps 0..9, one row each)
    if (warp < 10) {
        const int j = warp;
        const int idx = g_idx[b][qs][qq * 10 + j];
        const float4* mrow = (const float4*)(mu  + ((size_t)(b * NT + idx)) * ND);
        const float4* vrow = (const float4*)(var + ((size_t)(b * NT + idx)) * ND);
        float lsum = 0.f, asum = 0.f;
#pragma unroll
        for (int it = 0; it < 4; ++it) {
            int f = lane + it * 32;
            float4 m4 = mrow[f], v4 = vrow[f];
            v4.x += FEPS; v4.y += FEPS; v4.z += FEPS; v4.w += FEPS;
            float4 r4 = make_float4(1.f / v4.x, 1.f / v4.y, 1.f / v4.z, 1.f / v4.w);
            float4 s4 = make_float4(m4.x * r4.x, m4.y * r4.y, m4.z * r4.z, m4.w * r4.w);
            ((float4*)(r_q + j * ND))[f] = r4;
            ((float4*)(s_q + j * ND))[f] = s4;
            lsum += __log2f(v4.x) + __log2f(v4.y) + __log2f(v4.z) + __log2f(v4.w);
            asum += m4.x * s4.x + m4.y * s4.y + m4.z * s4.z + m4.w * s4.w;
        }
        float red2 = warp_sum(asum + LN2F * lsum);
        if (lane == 0) Dq[j] = 0.5f * red2;
    }
    __syncthreads();

    float accinv[2] = {0.f, 0.f};
    for (int j = 0; j < 10; ++j) {
        const ulonglong2* rq2 = (const ulonglong2*)(r_q + j * ND);
        const ulonglong2* sq2 = (const ulonglong2*)(s_q + j * ND);
        unsigned long long acc[2] = {0, 0};
#pragma unroll
        for (int it = 0; it < 4; ++it) {
            ulonglong2 r2 = rq2[lane + it * 32];
            ulonglong2 s2 = sq2[lane + it * 32];
#pragma unroll
            for (int rr = 0; rr < 2; ++rr) {
                acc[rr] = ffma2(up[rr][2 * it],     r2.x, acc[rr]);
                acc[rr] = ffma2(up[rr][2 * it + 1], r2.y, acc[rr]);
                acc[rr] = ffma2(wp[rr][2 * it],     s2.x, acc[rr]);
                acc[rr] = ffma2(wp[rr][2 * it + 1], s2.y, acc[rr]);
            }
        }
#pragma unroll
        for (int rr = 0; rr < 2; ++rr) {
            float2 a2 = upk2(acc[rr]);
            float red2 = warp_sum(a2.x + a2.y);
            if (lane == 0) {
                float dist = 0.5f * red2 + Dq[j] - halfLp[rr] - 0.5f * (float)ND;
                accinv[rr] += 1.f / (dist + 1.f);
            }
        }
    }
    if (lane == 0) { sAct[warp] = accinv[0]; sBkg[warp] = accinv[1]; }
    __syncthreads();
    if (warp == 0) {
        float va = (lane < 20) ? sAct[lane] : 0.f;
        float vb = (lane < 20) ? sBkg[lane] : 0.f;
        va = warp_sum(va);
        vb = warp_sum(vb);
        if (lane == 0) {
            g_klp[b][blockIdx.x][0] = va;
            g_klp[b][blockIdx.x][1] = vb;
        }
    }
}

// warp handles 4 rows (r, r+8192, r+16384, r+24576): 4 independent load streams.
__global__ void __launch_bounds__(256) k_distill(const float* __restrict__ mu,
                                                 const float* __restrict__ mc) {
    const int lane = threadIdx.x & 31;
    const int wib  = threadIdx.x >> 5;
    const int gw   = blockIdx.x * 8 + wib;        // 0..8191
    float d[4] = {0.f, 0.f, 0.f, 0.f};
    float p[4] = {0.f, 0.f, 0.f, 0.f};
    float q[4] = {0.f, 0.f, 0.f, 0.f};
    const float4* a[4]; const float4* c[4];
#pragma unroll
    for (int r = 0; r < 4; ++r) {
        size_t row = (size_t)(gw + r * 8192) * ND;
        a[r] = (const float4*)(mu + row);
        c[r] = (const float4*)(mc + row);
    }
#pragma unroll
    for (int it = 0; it < 4; ++it) {
        int f = lane + it * 32;
#pragma unroll
        for (int r = 0; r < 4; ++r) {
            float4 x = a[r][f], y = c[r][f];
            d[r] += x.x * y.x + x.y * y.y + x.z * y.z + x.w * y.w;
            p[r] += x.x * x.x + x.y * x.y + x.z * x.z + x.w * x.w;
            q[r] += y.x * y.x + y.y * y.y + y.z * y.z + y.w * y.w;
        }
    }
#pragma unroll
    for (int r = 0; r < 4; ++r) {
#pragma unroll
        for (int o = 16; o; o >>= 1) {
            d[r] += __shfl_down_sync(0xffffffffu, d[r], o);
            p[r] += __shfl_down_sync(0xffffffffu, p[r], o);
            q[r] += __shfl_down_sync(0xffffffffu, q[r], o);
        }
    }
    __shared__ double bs[8];
    if (lane == 0) {
        double loc = 0.0;
#pragma unroll
        for (int r = 0; r < 4; ++r) {
            float s = d[r] / (fmaxf(sqrtf(p[r]), 1e-12f) * fmaxf(sqrtf(q[r]), 1e-12f));
            loc += (double)((s + 1.f) * 0.5f);
        }
        bs[wib] = loc;
    }
    __syncthreads();
    if (threadIdx.x == 0) {
        double s = 0.0;
        for (int w = 0; w < 8; ++w) s += bs[w];
        g_dpart[blockIdx.x] = s;
    }
}

// grid 20: block i computes sum_j (sim(i,j) - delta_ij)^2 -> g_opart[i]
__global__ void __launch_bounds__(256) k_ortho(const float* __restrict__ tf) {
    __shared__ float e[NC * ND];      // 40 KB
    __shared__ float inv_n[NC];
    __shared__ float part[8];
    const int i = blockIdx.x;
    const int tid = threadIdx.x;
    const int warp = tid >> 5, lane = tid & 31;   // 8 warps
    for (int k = tid; k < NC * ND; k += 256) e[k] = tf[k];
    __syncthreads();
    for (int r = warp; r < NC; r += 8) {
        float s = 0.f;
        for (int d = lane; d < ND; d += 32) { float v = e[r * ND + d]; s += v * v; }
        s = warp_sum(s);
        if (lane == 0) inv_n[r] = 1.f / fmaxf(sqrtf(s), 1e-12f);
    }
    __syncthreads();
    float acc = 0.f;
    for (int j = warp; j < NC; j += 8) {
        float s = 0.f;
        for (int d = lane; d < ND; d += 32) s += e[i * ND + d] * e[j * ND + d];
        s = warp_sum(s);
        if (lane == 0) {
            float m = s * inv_n[i] * inv_n[j] - ((i == j) ? 1.f : 0.f);
            acc += m * m;
        }
    }
    if (lane == 0) part[warp] = acc;
    __syncthreads();
    if (tid == 0) {
        float s = 0.f;
        for (int w = 0; w < 8; ++w) s += part[w];
        g_opart[i] = s;
    }
}

// single block scalar finalization: pure reductions + logs
__global__ void __launch_bounds__(256) k_fin(float* __restrict__ out, int out_size) {
    __shared__ double dpartial[8];
    const int tid = threadIdx.x;
    const int warp = tid >> 5, lane = tid & 31;
    double dl = 0.0;
#pragma unroll
    for (int i = 0; i < 4; ++i) dl += g_dpart[tid + i * 256];
    dl = warp_dsum(dl);
    if (lane == 0) dpartial[warp] = dl;
    __syncthreads();
    if (tid == 0) {
        double ds = 0.0;
        for (int w = 0; w < 8; ++w) ds += dpartial[w];
        float distill = -logf((float)(ds / (double)(NB * NT)));
        float os = 0.f;
        for (int i = 0; i < NC; ++i) os += g_opart[i];
        float ortho = sqrtf(os);
        const float inv_pairs = 1.f / (float)(KH * KE);
        float act = 0.f, bkg = 0.f;
        for (int b = 0; b < NB; ++b) {
            float c0 = 0.f, c1 = 0.f, c2 = 0.f, c3 = 0.f;
            for (int x = 0; x < 4; ++x) { c0 += g_klp[b][x][0]; c3 += g_klp[b][x][1]; }
            for (int x = 4; x < 8; ++x) { c1 += g_klp[b][x][0]; c2 += g_klp[b][x][1]; }
            act += -(logf(c0 * inv_pairs) + logf(1.f - c1 * inv_pairs));
            bkg += -(logf(c2 * inv_pairs) + logf(1.f - c3 * inv_pairs));
        }
        act /= (float)NB;
        bkg /= (float)NB;
        float total = distill + act + bkg + ortho;
        float vals[5] = {total, distill, act, bkg, ortho};
        for (int i = 0; i < out_size && i < 5; ++i) out[i] = vals[i];
    }
}

// ---------------- launch (fork/join: distill overlaps the selection chain) ----
extern "C" void kernel_launch(void* const* d_in, const int* in_sizes, int n_in,
                              void* d_out, int out_size) {
    const float* attn      = (const float*)d_in[0];
    const float* mu        = (const float*)d_in[1];
    const float* var       = (const float*)d_in[2];
    const float* mu_clip   = (const float*)d_in[3];
    const float* text_feat = (const float*)d_in[4];
    const float* dmask     = (const float*)d_in[5];
    float* out = (float*)d_out;

    static cudaStream_t sB = nullptr;
    static cudaEvent_t evFork = nullptr, evJoin = nullptr;
    if (sB == nullptr) {
        cudaStreamCreateWithFlags(&sB, cudaStreamNonBlocking);
        cudaEventCreateWithFlags(&evFork, cudaEventDisableTiming);
        cudaEventCreateWithFlags(&evJoin, cudaEventDisableTiming);
    }

    const int kl_smem = 2 * 10 * ND * (int)sizeof(float);   // 40 KB

    // fork: distill on sB
    cudaEventRecord(evFork, 0);
    cudaStreamWaitEvent(sB, evFork, 0);
    k_distill<<<1024, 256, 0, sB>>>(mu, mu_clip);
    cudaEventRecord(evJoin, sB);

    // chain A on main stream (hidden under distill)
    k_topk<<<dim3(4, NB), 512>>>(attn, dmask);
    k_kl<<<dim3(8, NB), 640, kl_smem>>>(mu, var);
    k_ortho<<<NC, 256>>>(text_feat);

    // join + tiny scalar finalize
    cudaStreamWaitEvent(0, evJoin, 0);
    k_fin<<<1, 256>>>(out, out_size);
}

// round 6
// speedup vs baseline: 1.6989x; 1.1524x over previous
#include <cuda_runtime.h>
#include <math.h>

#define NB 16
#define NT 2048
#define ND 512
#define NC 20
#define KE 40
#define KH 20
#define FEPS 1e-5f
#define LN2F 0.69314718055994531f

// ---------------- scratch (write-only slots, no zeroing needed) ----------------
__device__ int    g_idx[NB][4][KE];     // 0=easy_act,1=easy_bkg,2=hard_act,3=hard_bkg
__device__ float  g_klp[NB][8][2];      // per (b, qchunk): [0]=vs hard_act, [1]=vs hard_bkg
__device__ double g_dpart[2048];        // distill per-block partials
__device__ float  g_opart[NC];          // ortho per-row partial sums of squares

// ---------------- helpers ----------------
__device__ __forceinline__ float warp_sum(float v) {
#pragma unroll
    for (int o = 16; o; o >>= 1) v += __shfl_down_sync(0xffffffffu, v, o);
    return v;
}
__device__ __forceinline__ float warp_max(float v) {
#pragma unroll
    for (int o = 16; o; o >>= 1) v = fmaxf(v, __shfl_down_sync(0xffffffffu, v, o));
    return v;
}
__device__ __forceinline__ double warp_dsum(double v) {
#pragma unroll
    for (int o = 16; o; o >>= 1) v += __shfl_down_sync(0xffffffffu, v, o);
    return v;
}
__device__ __forceinline__ unsigned long long pk2(float lo, float hi) {
    unsigned long long r;
    asm("mov.b64 %0, {%1, %2};" : "=l"(r) : "f"(lo), "f"(hi));
    return r;
}
__device__ __forceinline__ float2 upk2(unsigned long long v) {
    float2 f;
    asm("mov.b64 {%0, %1}, %2;" : "=f"(f.x), "=f"(f.y) : "l"(v));
    return f;
}
__device__ __forceinline__ unsigned long long ffma2(unsigned long long a,
                                                   unsigned long long b,
                                                   unsigned long long c) {
    unsigned long long d;
    asm("fma.rn.f32x2 %0, %1, %2, %3;" : "=l"(d) : "l"(a), "l"(b), "l"(c));
    return d;
}

// Descending radix select: bit pattern of the value at rank k (0-indexed desc).
// All scores >= 0 so bit order == value order. Called uniformly by the block.
__device__ unsigned radix_select_desc(const float* sc, int n, int k,
                                      unsigned* hist, unsigned* shc) {
    const int tid = threadIdx.x, nthr = blockDim.x;
    unsigned prefix = 0, pmask = 0;
#pragma unroll
    for (int level = 0; level < 4; ++level) {
        const int shift = 24 - 8 * level;
        for (int i = tid; i < 256; i += nthr) hist[i] = 0;
        __syncthreads();
        for (int i = tid; i < n; i += nthr) {
            unsigned u = __float_as_uint(sc[i]);
            bool ok = ((u & pmask) == prefix);
            unsigned d = ok ? ((u >> shift) & 255u) : 0x100u;
            unsigned mm = __match_any_sync(0xffffffffu, d);
            if (ok && ((tid & 31) == __ffs(mm) - 1))
                atomicAdd(&hist[d], (unsigned)__popc(mm));
        }
        __syncthreads();
        if (tid < 32) {
            const int l = tid;
            unsigned c[8]; unsigned lsum = 0;
#pragma unroll
            for (int i = 0; i < 8; ++i) { c[i] = hist[l * 8 + i]; lsum += c[i]; }
            unsigned v = lsum;
#pragma unroll
            for (int off = 1; off < 32; off <<= 1) {
                unsigned t = __shfl_down_sync(0xffffffffu, v, off);
                if (l + off < 32) v += t;
            }
            unsigned cum = v - lsum;          // elements in higher bins
            int found = -1; unsigned nk = 0;
#pragma unroll
            for (int i = 7; i >= 0; --i) {
                if (found < 0 && (unsigned)k >= cum && (unsigned)k < cum + c[i]) {
                    found = l * 8 + i; nk = (unsigned)k - cum;
                }
                cum += c[i];
            }
            if (found >= 0) { shc[0] = (unsigned)found; shc[1] = nk; }
        }
        __syncthreads();
        prefix |= shc[0] << shift;
        pmask  |= 0xFFu << shift;
        k = (int)shc[1];
        __syncthreads();
    }
    return prefix;
}

// ---------------- kernels ----------------
// One block per (score_set s, batch b): self-contained (median computed locally
// for s>=2), emits top-K index set with exact top_k tie-break (lowest index).
__global__ void __launch_bounds__(512) k_topk(const float* __restrict__ attn,
                                              const float* __restrict__ dmask) {
    __shared__ float sa[NT];
    __shared__ float ss[NT];
    __shared__ unsigned char sab[NT];
    __shared__ unsigned hist[256];
    __shared__ unsigned shc[2];
    __shared__ unsigned bm[NT / 32];
    __shared__ unsigned pfx[NT / 32];
    __shared__ float red[16];
    __shared__ int s_cnt;
    __shared__ int s_cntGE;
    __shared__ float s_maxLess;
    const int s = blockIdx.x, b = blockIdx.y, tid = threadIdx.x;
    const int warp = tid >> 5, lane = tid & 31;

    float lmax = 0.f;
    for (int t = tid; t < NT; t += 512) {
        float v = attn[b * NT + t];
        sa[t] = v;
        lmax = fmaxf(lmax, v);
    }
    lmax = warp_max(lmax);
    if (lane == 0) red[warp] = lmax;
    if (tid == 0) { s_cntGE = 0; s_maxLess = 0.f; }
    __syncthreads();
    float amax = red[0];
#pragma unroll
    for (int w = 1; w < 16; ++w) amax = fmaxf(amax, red[w]);

    if (s >= 2) {
        // exact median: v1 = rank1023 via radix select; v2 = rank1024 via one pass
        unsigned v1u = radix_select_desc(sa, NT, 1023, hist, shc);
        const float v1 = __uint_as_float(v1u);
        int cnt = 0; float ml = 0.f;
        for (int t = tid; t < NT; t += 512) {
            float x = sa[t];
            if (x >= v1) ++cnt; else ml = fmaxf(ml, x);
        }
#pragma unroll
        for (int o = 16; o; o >>= 1) {
            cnt += __shfl_down_sync(0xffffffffu, cnt, o);
            ml = fmaxf(ml, __shfl_down_sync(0xffffffffu, ml, o));
        }
        if (lane == 0) {
            atomicAdd(&s_cntGE, cnt);
            atomicMax((int*)&s_maxLess, __float_as_int(ml));   // floats >= 0
        }
        __syncthreads();
        float v2 = (s_cntGE >= 1025) ? v1 : s_maxLess;
        float med = 0.5f * (v1 + v2);
        for (int t = tid; t < NT; t += 512) sab[t] = (sa[t] > med) ? 1 : 0;
        __syncthreads();
    }

    for (int t = tid; t < NT; t += 512) {
        float a = sa[t];
        float v;
        if (s == 0) v = a * dmask[b * NT + t];
        else if (s == 1) v = (amax - a) * dmask[b * NT + t];
        else {
            int bm3 = (t >= 3) ? (int)sab[t - 3] : 0;
            int bm2 = (t >= 2) ? (int)sab[t - 2] : 0;
            int bm1 = (t >= 1) ? (int)sab[t - 1] : 0;
            int b0  = (int)sab[t];
            int bp1 = (t + 1 < NT) ? (int)sab[t + 1] : 0;
            int bp2 = (t + 2 < NT) ? (int)sab[t + 2] : 0;
            int bp3 = (t + 3 < NT) ? (int)sab[t + 3] : 0;
            if (s == 2) {
                int er3 = bm1 & b0 & bp1;
                int er7 = er3 & bm3 & bm2 & bp2 & bp3;
                v = a * (float)(er3 & (er7 ^ 1));
            } else {
                int dl3 = bm1 | b0 | bp1;
                int dl7 = dl3 | bm3 | bm2 | bp2 | bp3;
                v = a * (float)(dl7 & (dl3 ^ 1));
            }
        }
        ss[t] = v;
    }
    if (tid == 0) s_cnt = 0;
    for (int i = tid; i < NT / 32; i += 512) bm[i] = 0;
    __syncthreads();
    const int K = (s < 2) ? KE : KH;
    unsigned vk = radix_select_desc(ss, NT, K - 1, hist, shc);
    const float fvk = __uint_as_float(vk);
    for (int t = tid; t < NT; t += 512) {
        float v = ss[t];
        if (v > fvk) {
            int p = atomicAdd(&s_cnt, 1);
            g_idx[b][s][p] = t;
        } else if (v == fvk) {
            atomicOr(&bm[t >> 5], 1u << (t & 31));
        }
    }
    __syncthreads();
    if (tid < 32) {
        const int l = tid;
        unsigned p0 = __popc(bm[2 * l]), p1 = __popc(bm[2 * l + 1]);
        unsigned ls = p0 + p1, v = ls;
#pragma unroll
        for (int off = 1; off < 32; off <<= 1) {
            unsigned t2 = __shfl_up_sync(0xffffffffu, v, off);
            if (l >= off) v += t2;
        }
        unsigned excl = v - ls;
        pfx[2 * l] = excl;
        pfx[2 * l + 1] = excl + p0;
    }
    __syncthreads();
    const int base = s_cnt;
    const int m = K - base;
    for (int t = tid; t < NT; t += 512) {
        if (ss[t] == fvk) {
            int r = (int)(pfx[t >> 5] + __popc(bm[t >> 5] & ((1u << (t & 31)) - 1u)));
            if (r < m) g_idx[b][s][base + r] = t;
        }
    }
}

// grid (8, NB): blockIdx.x = qs*4 + qquarter. 640 threads = 20 warps.
__global__ void __launch_bounds__(640, 1) k_kl(const float* __restrict__ mu,
                                               const float* __restrict__ var) {
    extern __shared__ float sm[];
    float* r_q = sm;              // [10][ND]
    float* s_q = sm + 10 * ND;    // [10][ND]
    __shared__ float Dq[10];
    __shared__ float sAct[20], sBkg[20];
    const int qs = blockIdx.x >> 2;
    const int qq = blockIdx.x & 3;
    const int b  = blockIdx.y;
    const int warp = threadIdx.x >> 5;   // 0..19
    const int lane = threadIdx.x & 31;

    // stage p rows in registers (all warps)
    unsigned long long up[2][8], wp[2][8];
    float halfLp[2];
#pragma unroll
    for (int rr = 0; rr < 2; ++rr) {
        const int idx = g_idx[b][2 + rr][warp];
        const float4* mrow = (const float4*)(mu  + ((size_t)(b * NT + idx)) * ND);
        const float4* vrow = (const float4*)(var + ((size_t)(b * NT + idx)) * ND);
        float lsum = 0.f;
#pragma unroll
        for (int it = 0; it < 4; ++it) {
            int f = lane + it * 32;
            float4 m4 = mrow[f], v4 = vrow[f];
            v4.x += FEPS; v4.y += FEPS; v4.z += FEPS; v4.w += FEPS;
            up[rr][2 * it]     = pk2(m4.x * m4.x + v4.x, m4.y * m4.y + v4.y);
            up[rr][2 * it + 1] = pk2(m4.z * m4.z + v4.z, m4.w * m4.w + v4.w);
            wp[rr][2 * it]     = pk2(-2.f * m4.x, -2.f * m4.y);
            wp[rr][2 * it + 1] = pk2(-2.f * m4.z, -2.f * m4.w);
            lsum += __log2f(v4.x) + __log2f(v4.y) + __log2f(v4.z) + __log2f(v4.w);
        }
        lsum = warp_sum(lsum);
        halfLp[rr] = 0.5f * LN2F * __shfl_sync(0xffffffffu, lsum, 0);
    }

    // stage q rows (warps 0..9, one row each)
    if (warp < 10) {
        const int j = warp;
        const int idx = g_idx[b][qs][qq * 10 + j];
        const float4* mrow = (const float4*)(mu  + ((size_t)(b * NT + idx)) * ND);
        const float4* vrow = (const float4*)(var + ((size_t)(b * NT + idx)) * ND);
        float lsum = 0.f, asum = 0.f;
#pragma unroll
        for (int it = 0; it < 4; ++it) {
            int f = lane + it * 32;
            float4 m4 = mrow[f], v4 = vrow[f];
            v4.x += FEPS; v4.y += FEPS; v4.z += FEPS; v4.w += FEPS;
            float4 r4 = make_float4(1.f / v4.x, 1.f / v4.y, 1.f / v4.z, 1.f / v4.w);
            float4 s4 = make_float4(m4.x * r4.x, m4.y * r4.y, m4.z * r4.z, m4.w * r4.w);
            ((float4*)(r_q + j * ND))[f] = r4;
            ((float4*)(s_q + j * ND))[f] = s4;
            lsum += __log2f(v4.x) + __log2f(v4.y) + __log2f(v4.z) + __log2f(v4.w);
            asum += m4.x * s4.x + m4.y * s4.y + m4.z * s4.z + m4.w * s4.w;
        }
        float red2 = warp_sum(asum + LN2F * lsum);
        if (lane == 0) Dq[j] = 0.5f * red2;
    }
    __syncthreads();

    float accinv[2] = {0.f, 0.f};
#pragma unroll 2
    for (int j = 0; j < 10; ++j) {
        const ulonglong2* rq2 = (const ulonglong2*)(r_q + j * ND);
        const ulonglong2* sq2 = (const ulonglong2*)(s_q + j * ND);
        unsigned long long acc[2] = {0, 0};
#pragma unroll
        for (int it = 0; it < 4; ++it) {
            ulonglong2 r2 = rq2[lane + it * 32];
            ulonglong2 s2 = sq2[lane + it * 32];
#pragma unroll
            for (int rr = 0; rr < 2; ++rr) {
                acc[rr] = ffma2(up[rr][2 * it],     r2.x, acc[rr]);
                acc[rr] = ffma2(up[rr][2 * it + 1], r2.y, acc[rr]);
                acc[rr] = ffma2(wp[rr][2 * it],     s2.x, acc[rr]);
                acc[rr] = ffma2(wp[rr][2 * it + 1], s2.y, acc[rr]);
            }
        }
        float2 a0 = upk2(acc[0]);
        float2 a1 = upk2(acc[1]);
        float v0 = a0.x + a0.y;
        float v1 = a1.x + a1.y;
#pragma unroll
        for (int o = 16; o; o >>= 1) {
            v0 += __shfl_down_sync(0xffffffffu, v0, o);
            v1 += __shfl_down_sync(0xffffffffu, v1, o);
        }
        if (lane == 0) {
            float d0 = 0.5f * v0 + Dq[j] - halfLp[0] - 0.5f * (float)ND;
            float d1 = 0.5f * v1 + Dq[j] - halfLp[1] - 0.5f * (float)ND;
            accinv[0] += 1.f / (d0 + 1.f);
            accinv[1] += 1.f / (d1 + 1.f);
        }
    }
    if (lane == 0) { sAct[warp] = accinv[0]; sBkg[warp] = accinv[1]; }
    __syncthreads();
    if (warp == 0) {
        float va = (lane < 20) ? sAct[lane] : 0.f;
        float vb = (lane < 20) ? sBkg[lane] : 0.f;
        va = warp_sum(va);
        vb = warp_sum(vb);
        if (lane == 0) {
            g_klp[b][blockIdx.x][0] = va;
            g_klp[b][blockIdx.x][1] = vb;
        }
    }
}

// warp handles 2 rows (gw, gw+16384); streaming loads (no reuse downstream).
__global__ void __launch_bounds__(256) k_distill(const float* __restrict__ mu,
                                                 const float* __restrict__ mc) {
    const int lane = threadIdx.x & 31;
    const int wib  = threadIdx.x >> 5;
    const int gw   = blockIdx.x * 8 + wib;        // 0..16383
    const size_t r0 = (size_t)gw * ND;
    const size_t r1 = (size_t)(gw + 16384) * ND;
    const float4* a0 = (const float4*)(mu + r0);
    const float4* c0 = (const float4*)(mc + r0);
    const float4* a1 = (const float4*)(mu + r1);
    const float4* c1 = (const float4*)(mc + r1);
    float d0 = 0.f, p0 = 0.f, q0 = 0.f;
    float d1 = 0.f, p1 = 0.f, q1 = 0.f;
#pragma unroll
    for (int it = 0; it < 4; ++it) {
        int f = lane + it * 32;
        float4 x0 = __ldcs(&a0[f]);
        float4 y0 = __ldcs(&c0[f]);
        float4 x1 = __ldcs(&a1[f]);
        float4 y1 = __ldcs(&c1[f]);
        d0 += x0.x * y0.x + x0.y * y0.y + x0.z * y0.z + x0.w * y0.w;
        p0 += x0.x * x0.x + x0.y * x0.y + x0.z * x0.z + x0.w * x0.w;
        q0 += y0.x * y0.x + y0.y * y0.y + y0.z * y0.z + y0.w * y0.w;
        d1 += x1.x * y1.x + x1.y * y1.y + x1.z * y1.z + x1.w * y1.w;
        p1 += x1.x * x1.x + x1.y * x1.y + x1.z * x1.z + x1.w * x1.w;
        q1 += y1.x * y1.x + y1.y * y1.y + y1.z * y1.z + y1.w * y1.w;
    }
#pragma unroll
    for (int o = 16; o; o >>= 1) {
        d0 += __shfl_down_sync(0xffffffffu, d0, o);
        p0 += __shfl_down_sync(0xffffffffu, p0, o);
        q0 += __shfl_down_sync(0xffffffffu, q0, o);
        d1 += __shfl_down_sync(0xffffffffu, d1, o);
        p1 += __shfl_down_sync(0xffffffffu, p1, o);
        q1 += __shfl_down_sync(0xffffffffu, q1, o);
    }
    __shared__ double bs[8];
    if (lane == 0) {
        float s0 = d0 / (fmaxf(sqrtf(p0), 1e-12f) * fmaxf(sqrtf(q0), 1e-12f));
        float s1 = d1 / (fmaxf(sqrtf(p1), 1e-12f) * fmaxf(sqrtf(q1), 1e-12f));
        bs[wib] = (double)((s0 + 1.f) * 0.5f) + (double)((s1 + 1.f) * 0.5f);
    }
    __syncthreads();
    if (threadIdx.x == 0) {
        double s = 0.0;
        for (int w = 0; w < 8; ++w) s += bs[w];
        g_dpart[blockIdx.x] = s;
    }
}

// grid 20, 256 thr: block i computes sum_j (sim(i,j) - delta_ij)^2 -> g_opart[i]
// float4 smem + 4 independent accumulators per dot (short dep chains).
__global__ void __launch_bounds__(256) k_ortho(const float* __restrict__ tf) {
    __shared__ float e[NC * ND];      // 40 KB
    __shared__ float inv_n[NC];
    __shared__ float part[8];
    const int i = blockIdx.x;
    const int tid = threadIdx.x;
    const int warp = tid >> 5, lane = tid & 31;   // 8 warps
    for (int k = tid; k < NC * (ND / 4); k += 256)
        ((float4*)e)[k] = ((const float4*)tf)[k];
    __syncthreads();
    // norms: warp w covers rows w, w+8, (w<4: w+16)
    for (int r = warp; r < NC; r += 8) {
        const float4* er = (const float4*)(e + r * ND);
        float4 acc = make_float4(0.f, 0.f, 0.f, 0.f);
#pragma unroll
        for (int it = 0; it < 4; ++it) {
            float4 v = er[lane + it * 32];
            acc.x += v.x * v.x; acc.y += v.y * v.y;
            acc.z += v.z * v.z; acc.w += v.w * v.w;
        }
        float s = warp_sum(acc.x + acc.y + acc.z + acc.w);
        if (lane == 0) inv_n[r] = 1.f / fmaxf(sqrtf(s), 1e-12f);
    }
    __syncthreads();
    const float4* ei = (const float4*)(e + i * ND);
    float accp = 0.f;
    for (int j = warp; j < NC; j += 8) {
        const float4* ej = (const float4*)(e + j * ND);
        float4 acc = make_float4(0.f, 0.f, 0.f, 0.f);
#pragma unroll
        for (int it = 0; it < 4; ++it) {
            int f = lane + it * 32;
            float4 x = ei[f], y = ej[f];
            acc.x += x.x * y.x; acc.y += x.y * y.y;
            acc.z += x.z * y.z; acc.w += x.w * y.w;
        }
        float s = warp_sum(acc.x + acc.y + acc.z + acc.w);
        if (lane == 0) {
            float m = s * inv_n[i] * inv_n[j] - ((i == j) ? 1.f : 0.f);
            accp += m * m;
        }
    }
    if (lane == 0) part[warp] = accp;
    __syncthreads();
    if (tid == 0) {
        float s = 0.f;
        for (int w = 0; w < 8; ++w) s += part[w];
        g_opart[i] = s;
    }
}

// single block scalar finalization: pure reductions + logs
__global__ void __launch_bounds__(256) k_fin(float* __restrict__ out, int out_size) {
    __shared__ double dpartial[8];
    const int tid = threadIdx.x;
    const int warp = tid >> 5, lane = tid & 31;
    double dl = 0.0;
#pragma unroll
    for (int i = 0; i < 8; ++i) dl += g_dpart[tid + i * 256];
    dl = warp_dsum(dl);
    if (lane == 0) dpartial[warp] = dl;
    __syncthreads();
    if (tid == 0) {
        double ds = 0.0;
        for (int w = 0; w < 8; ++w) ds += dpartial[w];
        float distill = -logf((float)(ds / (double)(NB * NT)));
        float os = 0.f;
        for (int i = 0; i < NC; ++i) os += g_opart[i];
        float ortho = sqrtf(os);
        const float inv_pairs = 1.f / (float)(KH * KE);
        float act = 0.f, bkg = 0.f;
        for (int b = 0; b < NB; ++b) {
            float c0 = 0.f, c1 = 0.f, c2 = 0.f, c3 = 0.f;
            for (int x = 0; x < 4; ++x) { c0 += g_klp[b][x][0]; c3 += g_klp[b][x][1]; }
            for (int x = 4; x < 8; ++x) { c1 += g_klp[b][x][0]; c2 += g_klp[b][x][1]; }
            act += -(logf(c0 * inv_pairs) + logf(1.f - c1 * inv_pairs));
            bkg += -(logf(c2 * inv_pairs) + logf(1.f - c3 * inv_pairs));
        }
        act /= (float)NB;
        bkg /= (float)NB;
        float total = distill + act + bkg + ortho;
        float vals[5] = {total, distill, act, bkg, ortho};
        for (int i = 0; i < out_size && i < 5; ++i) out[i] = vals[i];
    }
}

// ---- launch: 3-way fork (distill | ortho | topk->kl), join, finalize ----
extern "C" void kernel_launch(void* const* d_in, const int* in_sizes, int n_in,
                              void* d_out, int out_size) {
    const float* attn      = (const float*)d_in[0];
    const float* mu        = (const float*)d_in[1];
    const float* var       = (const float*)d_in[2];
    const float* mu_clip   = (const float*)d_in[3];
    const float* text_feat = (const float*)d_in[4];
    const float* dmask     = (const float*)d_in[5];
    float* out = (float*)d_out;

    static cudaStream_t sB = nullptr, sC = nullptr;
    static cudaEvent_t evFork = nullptr, evJoinB = nullptr, evJoinC = nullptr;
    if (sB == nullptr) {
        cudaStreamCreateWithFlags(&sB, cudaStreamNonBlocking);
        cudaStreamCreateWithFlags(&sC, cudaStreamNonBlocking);
        cudaEventCreateWithFlags(&evFork, cudaEventDisableTiming);
        cudaEventCreateWithFlags(&evJoinB, cudaEventDisableTiming);
        cudaEventCreateWithFlags(&evJoinC, cudaEventDisableTiming);
    }

    const int kl_smem = 2 * 10 * ND * (int)sizeof(float);   // 40 KB

    cudaEventRecord(evFork, 0);
    cudaStreamWaitEvent(sB, evFork, 0);
    cudaStreamWaitEvent(sC, evFork, 0);

    // stream B: distill (DRAM-bound, 128 MB)
    k_distill<<<2048, 256, 0, sB>>>(mu, mu_clip);
    cudaEventRecord(evJoinB, sB);

    // stream C: ortho (independent of everything)
    k_ortho<<<NC, 256, 0, sC>>>(text_feat);
    cudaEventRecord(evJoinC, sC);

    // main: selection chain
    k_topk<<<dim3(4, NB), 512>>>(attn, dmask);
    k_kl<<<dim3(8, NB), 640, kl_smem>>>(mu, var);

    // join + tiny scalar finalize
    cudaStreamWaitEvent(0, evJoinB, 0);
    cudaStreamWaitEvent(0, evJoinC, 0);
    k_fin<<<1, 256>>>(out, out_size);
}

// round 7
// speedup vs baseline: 2.2562x; 1.3280x over previous
#include <cuda_runtime.h>
#include <math.h>

#define NB 16
#define NT 2048
#define ND 512
#define NC 20
#define KE 40
#define KH 20
#define FEPS 1e-5f
#define LN2F 0.69314718055994531f
#define NDB 592   // distill grid (4 blocks/SM on 148 SMs)

// ---------------- scratch (write-only slots, no zeroing needed) ----------------
__device__ int    g_idx[NB][4][KE];     // 0=easy_act,1=easy_bkg,2=hard_act,3=hard_bkg
__device__ float  g_klp[NB][8][2];      // per (b, qchunk): [0]=vs hard_act, [1]=vs hard_bkg
__device__ double g_dpart[NDB];         // distill per-block partials
__device__ float  g_opart[NC];          // ortho per-row partial sums of squares

// ---------------- helpers ----------------
__device__ __forceinline__ float warp_sum(float v) {
#pragma unroll
    for (int o = 16; o; o >>= 1) v += __shfl_down_sync(0xffffffffu, v, o);
    return v;
}
__device__ __forceinline__ float warp_max(float v) {
#pragma unroll
    for (int o = 16; o; o >>= 1) v = fmaxf(v, __shfl_down_sync(0xffffffffu, v, o));
    return v;
}
__device__ __forceinline__ double warp_dsum(double v) {
#pragma unroll
    for (int o = 16; o; o >>= 1) v += __shfl_down_sync(0xffffffffu, v, o);
    return v;
}
__device__ __forceinline__ unsigned long long pk2(float lo, float hi) {
    unsigned long long r;
    asm("mov.b64 %0, {%1, %2};" : "=l"(r) : "f"(lo), "f"(hi));
    return r;
}
__device__ __forceinline__ float2 upk2(unsigned long long v) {
    float2 f;
    asm("mov.b64 {%0, %1}, %2;" : "=f"(f.x), "=f"(f.y) : "l"(v));
    return f;
}
__device__ __forceinline__ unsigned long long ffma2(unsigned long long a,
                                                   unsigned long long b,
                                                   unsigned long long c) {
    unsigned long long d;
    asm("fma.rn.f32x2 %0, %1, %2, %3;" : "=l"(d) : "l"(a), "l"(b), "l"(c));
    return d;
}

// Descending radix select: bit pattern of the value at rank k (0-indexed desc).
__device__ unsigned radix_select_desc(const float* sc, int n, int k,
                                      unsigned* hist, unsigned* shc) {
    const int tid = threadIdx.x, nthr = blockDim.x;
    unsigned prefix = 0, pmask = 0;
#pragma unroll
    for (int level = 0; level < 4; ++level) {
        const int shift = 24 - 8 * level;
        for (int i = tid; i < 256; i += nthr) hist[i] = 0;
        __syncthreads();
        for (int i = tid; i < n; i += nthr) {
            unsigned u = __float_as_uint(sc[i]);
            bool ok = ((u & pmask) == prefix);
            unsigned d = ok ? ((u >> shift) & 255u) : 0x100u;
            unsigned mm = __match_any_sync(0xffffffffu, d);
            if (ok && ((tid & 31) == __ffs(mm) - 1))
                atomicAdd(&hist[d], (unsigned)__popc(mm));
        }
        __syncthreads();
        if (tid < 32) {
            const int l = tid;
            unsigned c[8]; unsigned lsum = 0;
#pragma unroll
            for (int i = 0; i < 8; ++i) { c[i] = hist[l * 8 + i]; lsum += c[i]; }
            unsigned v = lsum;
#pragma unroll
            for (int off = 1; off < 32; off <<= 1) {
                unsigned t = __shfl_down_sync(0xffffffffu, v, off);
                if (l + off < 32) v += t;
            }
            unsigned cum = v - lsum;          // elements in higher bins
            int found = -1; unsigned nk = 0;
#pragma unroll
            for (int i = 7; i >= 0; --i) {
                if (found < 0 && (unsigned)k >= cum && (unsigned)k < cum + c[i]) {
                    found = l * 8 + i; nk = (unsigned)k - cum;
                }
                cum += c[i];
            }
            if (found >= 0) { shc[0] = (unsigned)found; shc[1] = nk; }
        }
        __syncthreads();
        prefix |= shc[0] << shift;
        pmask  |= 0xFFu << shift;
        k = (int)shc[1];
        __syncthreads();
    }
    return prefix;
}

// ---------------- kernels ----------------
__global__ void __launch_bounds__(512) k_topk(const float* __restrict__ attn,
                                              const float* __restrict__ dmask) {
    __shared__ float sa[NT];
    __shared__ float ss[NT];
    __shared__ unsigned char sab[NT];
    __shared__ unsigned hist[256];
    __shared__ unsigned shc[2];
    __shared__ unsigned bm[NT / 32];
    __shared__ unsigned pfx[NT / 32];
    __shared__ float red[16];
    __shared__ int s_cnt;
    __shared__ int s_cntGE;
    __shared__ float s_maxLess;
    const int s = blockIdx.x, b = blockIdx.y, tid = threadIdx.x;
    const int warp = tid >> 5, lane = tid & 31;

    float lmax = 0.f;
    for (int t = tid; t < NT; t += 512) {
        float v = attn[b * NT + t];
        sa[t] = v;
        lmax = fmaxf(lmax, v);
    }
    lmax = warp_max(lmax);
    if (lane == 0) red[warp] = lmax;
    if (tid == 0) { s_cntGE = 0; s_maxLess = 0.f; }
    __syncthreads();
    float amax = red[0];
#pragma unroll
    for (int w = 1; w < 16; ++w) amax = fmaxf(amax, red[w]);

    if (s >= 2) {
        unsigned v1u = radix_select_desc(sa, NT, 1023, hist, shc);
        const float v1 = __uint_as_float(v1u);
        int cnt = 0; float ml = 0.f;
        for (int t = tid; t < NT; t += 512) {
            float x = sa[t];
            if (x >= v1) ++cnt; else ml = fmaxf(ml, x);
        }
#pragma unroll
        for (int o = 16; o; o >>= 1) {
            cnt += __shfl_down_sync(0xffffffffu, cnt, o);
            ml = fmaxf(ml, __shfl_down_sync(0xffffffffu, ml, o));
        }
        if (lane == 0) {
            atomicAdd(&s_cntGE, cnt);
            atomicMax((int*)&s_maxLess, __float_as_int(ml));   // floats >= 0
        }
        __syncthreads();
        float v2 = (s_cntGE >= 1025) ? v1 : s_maxLess;
        float med = 0.5f * (v1 + v2);
        for (int t = tid; t < NT; t += 512) sab[t] = (sa[t] > med) ? 1 : 0;
        __syncthreads();
    }

    for (int t = tid; t < NT; t += 512) {
        float a = sa[t];
        float v;
        if (s == 0) v = a * dmask[b * NT + t];
        else if (s == 1) v = (amax - a) * dmask[b * NT + t];
        else {
            int bm3 = (t >= 3) ? (int)sab[t - 3] : 0;
            int bm2 = (t >= 2) ? (int)sab[t - 2] : 0;
            int bm1 = (t >= 1) ? (int)sab[t - 1] : 0;
            int b0  = (int)sab[t];
            int bp1 = (t + 1 < NT) ? (int)sab[t + 1] : 0;
            int bp2 = (t + 2 < NT) ? (int)sab[t + 2] : 0;
            int bp3 = (t + 3 < NT) ? (int)sab[t + 3] : 0;
            if (s == 2) {
                int er3 = bm1 & b0 & bp1;
                int er7 = er3 & bm3 & bm2 & bp2 & bp3;
                v = a * (float)(er3 & (er7 ^ 1));
            } else {
                int dl3 = bm1 | b0 | bp1;
                int dl7 = dl3 | bm3 | bm2 | bp2 | bp3;
                v = a * (float)(dl7 & (dl3 ^ 1));
            }
        }
        ss[t] = v;
    }
    if (tid == 0) s_cnt = 0;
    for (int i = tid; i < NT / 32; i += 512) bm[i] = 0;
    __syncthreads();
    const int K = (s < 2) ? KE : KH;
    unsigned vk = radix_select_desc(ss, NT, K - 1, hist, shc);
    const float fvk = __uint_as_float(vk);
    for (int t = tid; t < NT; t += 512) {
        float v = ss[t];
        if (v > fvk) {
            int p = atomicAdd(&s_cnt, 1);
            g_idx[b][s][p] = t;
        } else if (v == fvk) {
            atomicOr(&bm[t >> 5], 1u << (t & 31));
        }
    }
    __syncthreads();
    if (tid < 32) {
        const int l = tid;
        unsigned p0 = __popc(bm[2 * l]), p1 = __popc(bm[2 * l + 1]);
        unsigned ls = p0 + p1, v = ls;
#pragma unroll
        for (int off = 1; off < 32; off <<= 1) {
            unsigned t2 = __shfl_up_sync(0xffffffffu, v, off);
            if (l >= off) v += t2;
        }
        unsigned excl = v - ls;
        pfx[2 * l] = excl;
        pfx[2 * l + 1] = excl + p0;
    }
    __syncthreads();
    const int base = s_cnt;
    const int m = K - base;
    for (int t = tid; t < NT; t += 512) {
        if (ss[t] == fvk) {
            int r = (int)(pfx[t >> 5] + __popc(bm[t >> 5] & ((1u << (t & 31)) - 1u)));
            if (r < m) g_idx[b][s][base + r] = t;
        }
    }
}

// grid (8, NB): blockIdx.x = qs*4 + qquarter. 640 threads = 20 warps.
__global__ void __launch_bounds__(640, 1) k_kl(const float* __restrict__ mu,
                                               const float* __restrict__ var) {
    extern __shared__ float sm[];
    float* r_q = sm;              // [10][ND]
    float* s_q = sm + 10 * ND;    // [10][ND]
    __shared__ float Dq[10];
    __shared__ float sAct[20], sBkg[20];
    const int qs = blockIdx.x >> 2;
    const int qq = blockIdx.x & 3;
    const int b  = blockIdx.y;
    const int warp = threadIdx.x >> 5;   // 0..19
    const int lane = threadIdx.x & 31;

    unsigned long long up[2][8], wp[2][8];
    float halfLp[2];
#pragma unroll
    for (int rr = 0; rr < 2; ++rr) {
        const int idx = g_idx[b][2 + rr][warp];
        const float4* mrow = (const float4*)(mu  + ((size_t)(b * NT + idx)) * ND);
        const float4* vrow = (const float4*)(var + ((size_t)(b * NT + idx)) * ND);
        float lsum = 0.f;
#pragma unroll
        for (int it = 0; it < 4; ++it) {
            int f = lane + it * 32;
            float4 m4 = mrow[f], v4 = vrow[f];
            v4.x += FEPS; v4.y += FEPS; v4.z += FEPS; v4.w += FEPS;
            up[rr][2 * it]     = pk2(m4.x * m4.x + v4.x, m4.y * m4.y + v4.y);
            up[rr][2 * it + 1] = pk2(m4.z * m4.z + v4.z, m4.w * m4.w + v4.w);
            wp[rr][2 * it]     = pk2(-2.f * m4.x, -2.f * m4.y);
            wp[rr][2 * it + 1] = pk2(-2.f * m4.z, -2.f * m4.w);
            lsum += __log2f(v4.x) + __log2f(v4.y) + __log2f(v4.z) + __log2f(v4.w);
        }
        lsum = warp_sum(lsum);
        halfLp[rr] = 0.5f * LN2F * __shfl_sync(0xffffffffu, lsum, 0);
    }

    if (warp < 10) {
        const int j = warp;
        const int idx = g_idx[b][qs][qq * 10 + j];
        const float4* mrow = (const float4*)(mu  + ((size_t)(b * NT + idx)) * ND);
        const float4* vrow = (const float4*)(var + ((size_t)(b * NT + idx)) * ND);
        float lsum = 0.f, asum = 0.f;
#pragma unroll
        for (int it = 0; it < 4; ++it) {
            int f = lane + it * 32;
            float4 m4 = mrow[f], v4 = vrow[f];
            v4.x += FEPS; v4.y += FEPS; v4.z += FEPS; v4.w += FEPS;
            float4 r4 = make_float4(1.f / v4.x, 1.f / v4.y, 1.f / v4.z, 1.f / v4.w);
            float4 s4 = make_float4(m4.x * r4.x, m4.y * r4.y, m4.z * r4.z, m4.w * r4.w);
            ((float4*)(r_q + j * ND))[f] = r4;
            ((float4*)(s_q + j * ND))[f] = s4;
            lsum += __log2f(v4.x) + __log2f(v4.y) + __log2f(v4.z) + __log2f(v4.w);
            asum += m4.x * s4.x + m4.y * s4.y + m4.z * s4.z + m4.w * s4.w;
        }
        float red2 = warp_sum(asum + LN2F * lsum);
        if (lane == 0) Dq[j] = 0.5f * red2;
    }
    __syncthreads();

    float accinv[2] = {0.f, 0.f};
#pragma unroll 2
    for (int j = 0; j < 10; ++j) {
        const ulonglong2* rq2 = (const ulonglong2*)(r_q + j * ND);
        const ulonglong2* sq2 = (const ulonglong2*)(s_q + j * ND);
        unsigned long long aU0 = 0, aW0 = 0, aU1 = 0, aW1 = 0;
#pragma unroll
        for (int it = 0; it < 4; ++it) {
            ulonglong2 r2 = rq2[lane + it * 32];
            ulonglong2 s2 = sq2[lane + it * 32];
            aU0 = ffma2(up[0][2 * it],     r2.x, aU0);
            aU0 = ffma2(up[0][2 * it + 1], r2.y, aU0);
            aW0 = ffma2(wp[0][2 * it],     s2.x, aW0);
            aW0 = ffma2(wp[0][2 * it + 1], s2.y, aW0);
            aU1 = ffma2(up[1][2 * it],     r2.x, aU1);
            aU1 = ffma2(up[1][2 * it + 1], r2.y, aU1);
            aW1 = ffma2(wp[1][2 * it],     s2.x, aW1);
            aW1 = ffma2(wp[1][2 * it + 1], s2.y, aW1);
        }
        float2 u0 = upk2(aU0), w0 = upk2(aW0);
        float2 u1 = upk2(aU1), w1 = upk2(aW1);
        float v0 = u0.x + u0.y + w0.x + w0.y;
        float v1 = u1.x + u1.y + w1.x + w1.y;
#pragma unroll
        for (int o = 16; o; o >>= 1) {
            v0 += __shfl_down_sync(0xffffffffu, v0, o);
            v1 += __shfl_down_sync(0xffffffffu, v1, o);
        }
        if (lane == 0) {
            float d0 = 0.5f * v0 + Dq[j] - halfLp[0] - 0.5f * (float)ND;
            float d1 = 0.5f * v1 + Dq[j] - halfLp[1] - 0.5f * (float)ND;
            accinv[0] += 1.f / (d0 + 1.f);
            accinv[1] += 1.f / (d1 + 1.f);
        }
    }
    if (lane == 0) { sAct[warp] = accinv[0]; sBkg[warp] = accinv[1]; }
    __syncthreads();
    if (warp == 0) {
        float va = (lane < 20) ? sAct[lane] : 0.f;
        float vb = (lane < 20) ? sBkg[lane] : 0.f;
        va = warp_sum(va);
        vb = warp_sum(vb);
        if (lane == 0) {
            g_klp[b][blockIdx.x][0] = va;
            g_klp[b][blockIdx.x][1] = vb;
        }
    }
}

// persistent grid-stride (grid=NDB, 4 blocks/SM): leaves warp slots free for the
// chain kernels to co-schedule. Warp processes row pairs (row, row+16384).
__global__ void __launch_bounds__(256) k_distill(const float* __restrict__ mu,
                                                 const float* __restrict__ mc) {
    const int lane = threadIdx.x & 31;
    const int wib  = threadIdx.x >> 5;
    const int gw   = blockIdx.x * 8 + wib;
    const int nw   = gridDim.x * 8;
    double local = 0.0;
    for (int row = gw; row < 16384; row += nw) {
        const size_t r0 = (size_t)row * ND;
        const size_t r1 = (size_t)(row + 16384) * ND;
        const float4* a0 = (const float4*)(mu + r0);
        const float4* c0 = (const float4*)(mc + r0);
        const float4* a1 = (const float4*)(mu + r1);
        const float4* c1 = (const float4*)(mc + r1);
        float d0 = 0.f, p0 = 0.f, q0 = 0.f;
        float d1 = 0.f, p1 = 0.f, q1 = 0.f;
#pragma unroll
        for (int it = 0; it < 4; ++it) {
            int f = lane + it * 32;
            float4 x0 = __ldcs(&a0[f]);
            float4 y0 = __ldcs(&c0[f]);
            float4 x1 = __ldcs(&a1[f]);
            float4 y1 = __ldcs(&c1[f]);
            d0 += x0.x * y0.x + x0.y * y0.y + x0.z * y0.z + x0.w * y0.w;
            p0 += x0.x * x0.x + x0.y * x0.y + x0.z * x0.z + x0.w * x0.w;
            q0 += y0.x * y0.x + y0.y * y0.y + y0.z * y0.z + y0.w * y0.w;
            d1 += x1.x * y1.x + x1.y * y1.y + x1.z * y1.z + x1.w * y1.w;
            p1 += x1.x * x1.x + x1.y * x1.y + x1.z * x1.z + x1.w * x1.w;
            q1 += y1.x * y1.x + y1.y * y1.y + y1.z * y1.z + y1.w * y1.w;
        }
#pragma unroll
        for (int o = 16; o; o >>= 1) {
            d0 += __shfl_down_sync(0xffffffffu, d0, o);
            p0 += __shfl_down_sync(0xffffffffu, p0, o);
            q0 += __shfl_down_sync(0xffffffffu, q0, o);
            d1 += __shfl_down_sync(0xffffffffu, d1, o);
            p1 += __shfl_down_sync(0xffffffffu, p1, o);
            q1 += __shfl_down_sync(0xffffffffu, q1, o);
        }
        if (lane == 0) {
            float s0 = d0 / (fmaxf(sqrtf(p0), 1e-12f) * fmaxf(sqrtf(q0), 1e-12f));
            float s1 = d1 / (fmaxf(sqrtf(p1), 1e-12f) * fmaxf(sqrtf(q1), 1e-12f));
            local += (double)((s0 + 1.f) * 0.5f) + (double)((s1 + 1.f) * 0.5f);
        }
    }
    __shared__ double bs[8];
    if (lane == 0) bs[wib] = local;
    __syncthreads();
    if (threadIdx.x == 0) {
        double s = 0.0;
        for (int w = 0; w < 8; ++w) s += bs[w];
        g_dpart[blockIdx.x] = s;
    }
}

// grid 20, 256 thr: block i computes sum_j (sim(i,j) - delta_ij)^2 -> g_opart[i]
__global__ void __launch_bounds__(256) k_ortho(const float* __restrict__ tf) {
    __shared__ float e[NC * ND];
    __shared__ float inv_n[NC];
    __shared__ float part[8];
    const int i = blockIdx.x;
    const int tid = threadIdx.x;
    const int warp = tid >> 5, lane = tid & 31;
    for (int k = tid; k < NC * (ND / 4); k += 256)
        ((float4*)e)[k] = ((const float4*)tf)[k];
    __syncthreads();
    for (int r = warp; r < NC; r += 8) {
        const float4* er = (const float4*)(e + r * ND);
        float4 acc = make_float4(0.f, 0.f, 0.f, 0.f);
#pragma unroll
        for (int it = 0; it < 4; ++it) {
            float4 v = er[lane + it * 32];
            acc.x += v.x * v.x; acc.y += v.y * v.y;
            acc.z += v.z * v.z; acc.w += v.w * v.w;
        }
        float s = warp_sum(acc.x + acc.y + acc.z + acc.w);
        if (lane == 0) inv_n[r] = 1.f / fmaxf(sqrtf(s), 1e-12f);
    }
    __syncthreads();
    const float4* ei = (const float4*)(e + i * ND);
    float accp = 0.f;
    for (int j = warp; j < NC; j += 8) {
        const float4* ej = (const float4*)(e + j * ND);
        float4 acc = make_float4(0.f, 0.f, 0.f, 0.f);
#pragma unroll
        for (int it = 0; it < 4; ++it) {
            int f = lane + it * 32;
            float4 x = ei[f], y = ej[f];
            acc.x += x.x * y.x; acc.y += x.y * y.y;
            acc.z += x.z * y.z; acc.w += x.w * y.w;
        }
        float s = warp_sum(acc.x + acc.y + acc.z + acc.w);
        if (lane == 0) {
            float m = s * inv_n[i] * inv_n[j] - ((i == j) ? 1.f : 0.f);
            accp += m * m;
        }
    }
    if (lane == 0) part[warp] = accp;
    __syncthreads();
    if (tid == 0) {
        float s = 0.f;
        for (int w = 0; w < 8; ++w) s += part[w];
        g_opart[i] = s;
    }
}

// single block scalar finalization
__global__ void __launch_bounds__(256) k_fin(float* __restrict__ out, int out_size) {
    __shared__ double dpartial[8];
    const int tid = threadIdx.x;
    const int warp = tid >> 5, lane = tid & 31;
    double dl = 0.0;
#pragma unroll
    for (int i = 0; i < 3; ++i) {
        int idx = tid + i * 256;
        if (idx < NDB) dl += g_dpart[idx];
    }
    dl = warp_dsum(dl);
    if (lane == 0) dpartial[warp] = dl;
    __syncthreads();
    if (tid == 0) {
        double ds = 0.0;
        for (int w = 0; w < 8; ++w) ds += dpartial[w];
        float distill = -logf((float)(ds / (double)(NB * NT)));
        float os = 0.f;
        for (int i = 0; i < NC; ++i) os += g_opart[i];
        float ortho = sqrtf(os);
        const float inv_pairs = 1.f / (float)(KH * KE);
        float act = 0.f, bkg = 0.f;
        for (int b = 0; b < NB; ++b) {
            float c0 = 0.f, c1 = 0.f, c2 = 0.f, c3 = 0.f;
            for (int x = 0; x < 4; ++x) { c0 += g_klp[b][x][0]; c3 += g_klp[b][x][1]; }
            for (int x = 4; x < 8; ++x) { c1 += g_klp[b][x][0]; c2 += g_klp[b][x][1]; }
            act += -(logf(c0 * inv_pairs) + logf(1.f - c1 * inv_pairs));
            bkg += -(logf(c2 * inv_pairs) + logf(1.f - c3 * inv_pairs));
        }
        act /= (float)NB;
        bkg /= (float)NB;
        float total = distill + act + bkg + ortho;
        float vals[5] = {total, distill, act, bkg, ortho};
        for (int i = 0; i < out_size && i < 5; ++i) out[i] = vals[i];
    }
}

// ---- launch: priority fork (chain HIGH | distill LOW | ortho LOW), join, fin ----
extern "C" void kernel_launch(void* const* d_in, const int* in_sizes, int n_in,
                              void* d_out, int out_size) {
    const float* attn      = (const float*)d_in[0];
    const float* mu        = (const float*)d_in[1];
    const float* var       = (const float*)d_in[2];
    const float* mu_clip   = (const float*)d_in[3];
    const float* text_feat = (const float*)d_in[4];
    const float* dmask     = (const float*)d_in[5];
    float* out = (float*)d_out;

    static cudaStream_t sA = nullptr, sB = nullptr, sC = nullptr;
    static cudaEvent_t evFork = nullptr, evA = nullptr, evB = nullptr, evC = nullptr;
    if (sA == nullptr) {
        int lo, hi;
        cudaDeviceGetStreamPriorityRange(&lo, &hi);  // hi = highest priority
        cudaStreamCreateWithPriority(&sA, cudaStreamNonBlocking, hi);
        cudaStreamCreateWithPriority(&sB, cudaStreamNonBlocking, lo);
        cudaStreamCreateWithPriority(&sC, cudaStreamNonBlocking, lo);
        cudaEventCreateWithFlags(&evFork, cudaEventDisableTiming);
        cudaEventCreateWithFlags(&evA, cudaEventDisableTiming);
        cudaEventCreateWithFlags(&evB, cudaEventDisableTiming);
        cudaEventCreateWithFlags(&evC, cudaEventDisableTiming);
    }

    const int kl_smem = 2 * 10 * ND * (int)sizeof(float);   // 40 KB

    cudaEventRecord(evFork, 0);
    cudaStreamWaitEvent(sA, evFork, 0);
    cudaStreamWaitEvent(sB, evFork, 0);
    cudaStreamWaitEvent(sC, evFork, 0);

    // high-priority chain
    k_topk<<<dim3(4, NB), 512, 0, sA>>>(attn, dmask);
    k_kl<<<dim3(8, NB), 640, kl_smem, sA>>>(mu, var);
    cudaEventRecord(evA, sA);

    // low-priority bulk + ortho
    k_distill<<<NDB, 256, 0, sB>>>(mu, mu_clip);
    cudaEventRecord(evB, sB);
    k_ortho<<<NC, 256, 0, sC>>>(text_feat);
    cudaEventRecord(evC, sC);

    cudaStreamWaitEvent(0, evA, 0);
    cudaStreamWaitEvent(0, evB, 0);
    cudaStreamWaitEvent(0, evC, 0);
    k_fin<<<1, 256>>>(out, out_size);
}